// round 1
// baseline (speedup 1.0000x reference)
#include <cuda_runtime.h>

#define B_  2
#define S_  2048
#define D_  1024
#define H_  16
#define KS_ 64
#define NEG_BIG (-1.0e9f)

#define NTOK ((size_t)B_ * S_ * D_)   // 4,194,304 elements per [B,S,D] tensor

// Scratch: Q, K, V, Context  (4 x 16 MB). Static device array — no allocation.
__device__ __align__(16) float g_scratch[4 * B_ * S_ * D_];

// ---------------------------------------------------------------------------
// Generic fp32 GEMM:  C[M,N] = A[M,K] @ W[K,N] + bias[N]
// BM=BN=128, BK=8, 256 threads, 8x8 per thread. M%128==0, N%128==0, K%8==0.
// ---------------------------------------------------------------------------
__global__ void gemm128(const float* __restrict__ A, const float* __restrict__ W,
                        const float* __restrict__ bias, float* __restrict__ C,
                        int M, int N, int K) {
    __shared__ float As[8][128];   // transposed: As[k][m]
    __shared__ float Bs[8][128];

    int tid  = threadIdx.x;
    int row0 = blockIdx.y * 128;
    int col0 = blockIdx.x * 128;
    int tx = tid & 15;        // 0..15 -> 8 cols each
    int ty = tid >> 4;        // 0..15 -> 8 rows each

    int a_row = tid >> 1;            // 0..127
    int a_col = (tid & 1) * 4;       // 0 or 4
    int b_row = tid >> 5;            // 0..7
    int b_col = (tid & 31) * 4;      // 0..124

    const float* Aptr = A + (size_t)(row0 + a_row) * K + a_col;
    const float* Wptr = W + (size_t)b_row * N + col0 + b_col;

    float acc[8][8] = {};

    for (int k0 = 0; k0 < K; k0 += 8) {
        float4 av = *(const float4*)(Aptr + k0);
        As[a_col + 0][a_row] = av.x;
        As[a_col + 1][a_row] = av.y;
        As[a_col + 2][a_row] = av.z;
        As[a_col + 3][a_row] = av.w;
        float4 bv = *(const float4*)(Wptr + (size_t)k0 * N);
        *(float4*)&Bs[b_row][b_col] = bv;
        __syncthreads();

        #pragma unroll
        for (int kk = 0; kk < 8; kk++) {
            float ra[8], rb[8];
            #pragma unroll
            for (int i = 0; i < 8; i++) ra[i] = As[kk][ty * 8 + i];
            #pragma unroll
            for (int j = 0; j < 8; j++) rb[j] = Bs[kk][tx * 8 + j];
            #pragma unroll
            for (int i = 0; i < 8; i++)
                #pragma unroll
                for (int j = 0; j < 8; j++)
                    acc[i][j] = fmaf(ra[i], rb[j], acc[i][j]);
        }
        __syncthreads();
    }

    #pragma unroll
    for (int i = 0; i < 8; i++) {
        size_t r = row0 + ty * 8 + i;
        #pragma unroll
        for (int j = 0; j < 8; j += 4) {
            int c = col0 + tx * 8 + j;
            float4 o;
            o.x = acc[i][j + 0] + bias[c + 0];
            o.y = acc[i][j + 1] + bias[c + 1];
            o.z = acc[i][j + 2] + bias[c + 2];
            o.w = acc[i][j + 3] + bias[c + 3];
            *(float4*)&C[r * N + c] = o;
        }
    }
}

// ---------------------------------------------------------------------------
// Scores: out[bh,q,k] = (Q[b,q,h,:]·K[b,k,h,:]) / 8, * mask, zeros -> -1e9
// grid: (S/64 k-tiles, S/64 q-tiles, B*H). 256 threads, 4x4 per thread.
// ---------------------------------------------------------------------------
__global__ void score_kernel(const float* __restrict__ Q, const float* __restrict__ Kmat,
                             const float* __restrict__ mask, float* __restrict__ out) {
    __shared__ float Qs[64][65];
    __shared__ float Ks[64][65];

    int bh = blockIdx.z;
    int b  = bh >> 4;
    int h  = bh & 15;
    int q0 = blockIdx.y * 64;
    int k0 = blockIdx.x * 64;
    int tid = threadIdx.x;

    const float* Qbase = Q    + ((size_t)b * S_ + q0) * D_ + h * KS_;
    const float* Kbase = Kmat + ((size_t)b * S_ + k0) * D_ + h * KS_;

    for (int i = tid; i < 64 * 16; i += 256) {
        int r  = i >> 4;
        int c4 = (i & 15) << 2;
        float4 qv = *(const float4*)(Qbase + (size_t)r * D_ + c4);
        Qs[r][c4 + 0] = qv.x; Qs[r][c4 + 1] = qv.y;
        Qs[r][c4 + 2] = qv.z; Qs[r][c4 + 3] = qv.w;
        float4 kv = *(const float4*)(Kbase + (size_t)r * D_ + c4);
        Ks[r][c4 + 0] = kv.x; Ks[r][c4 + 1] = kv.y;
        Ks[r][c4 + 2] = kv.z; Ks[r][c4 + 3] = kv.w;
    }
    __syncthreads();

    int tx = tid & 15;
    int ty = tid >> 4;
    float acc[4][4] = {};

    #pragma unroll
    for (int d = 0; d < 64; d++) {
        float ra[4], rb[4];
        #pragma unroll
        for (int i = 0; i < 4; i++) ra[i] = Qs[ty * 4 + i][d];
        #pragma unroll
        for (int j = 0; j < 4; j++) rb[j] = Ks[tx * 4 + j][d];
        #pragma unroll
        for (int i = 0; i < 4; i++)
            #pragma unroll
            for (int j = 0; j < 4; j++)
                acc[i][j] = fmaf(ra[i], rb[j], acc[i][j]);
    }

    const float* mrow = mask + (size_t)b * S_ * S_;
    float* orow = out + (size_t)bh * S_ * S_;
    #pragma unroll
    for (int i = 0; i < 4; i++) {
        int qg = q0 + ty * 4 + i;
        #pragma unroll
        for (int j = 0; j < 4; j++) {
            int kg = k0 + tx * 4 + j;
            float s = acc[i][j] * 0.125f;           // 1/sqrt(64)
            s *= mrow[(size_t)qg * S_ + kg];
            if (s == 0.0f) s = NEG_BIG;
            orow[(size_t)qg * S_ + kg] = s;
        }
    }
}

// ---------------------------------------------------------------------------
// In-place row softmax over S_=2048 elements. One block per row, 256 threads.
// ---------------------------------------------------------------------------
__global__ void softmax_kernel(float* __restrict__ a) {
    __shared__ float buf[S_];
    __shared__ float red[8];

    size_t row = blockIdx.x;
    float* p = a + row * S_;
    int tid = threadIdx.x;

    float mx = -3.402823466e38f;
    for (int i = tid; i < S_; i += 256) {
        float v = p[i];
        buf[i] = v;
        mx = fmaxf(mx, v);
    }
    #pragma unroll
    for (int o = 16; o > 0; o >>= 1) mx = fmaxf(mx, __shfl_xor_sync(0xffffffffu, mx, o));
    if ((tid & 31) == 0) red[tid >> 5] = mx;
    __syncthreads();
    float bmx = red[0];
    #pragma unroll
    for (int i = 1; i < 8; i++) bmx = fmaxf(bmx, red[i]);
    __syncthreads();

    float sm = 0.0f;
    for (int i = tid; i < S_; i += 256) {
        float e = expf(buf[i] - bmx);
        buf[i] = e;
        sm += e;
    }
    #pragma unroll
    for (int o = 16; o > 0; o >>= 1) sm += __shfl_xor_sync(0xffffffffu, sm, o);
    if ((tid & 31) == 0) red[tid >> 5] = sm;
    __syncthreads();
    float tot = 0.0f;
    #pragma unroll
    for (int i = 0; i < 8; i++) tot += red[i];
    float inv = 1.0f / tot;

    for (int i = tid; i < S_; i += 256) p[i] = buf[i] * inv;
}

// ---------------------------------------------------------------------------
// Context: C[b,q,h,:] = sum_k align[bh,q,k] * V[b,k,h,:]
// Per (b,h): GEMM M=S_, N=64, K=S_.  grid: (S/64 q-tiles, B*H). 256 thr, 4x4.
// Output written directly into [B,S,D] layout.
// ---------------------------------------------------------------------------
__global__ void context_kernel(const float* __restrict__ A, const float* __restrict__ Vm,
                               float* __restrict__ C) {
    __shared__ float As[64][17];   // [m][k] with pad
    __shared__ float Bs[16][64];   // [k][n]

    int bh = blockIdx.y;
    int b  = bh >> 4;
    int h  = bh & 15;
    int q0 = blockIdx.x * 64;
    int tid = threadIdx.x;
    int tx = tid & 15;
    int ty = tid >> 4;

    const float* Arow  = A  + ((size_t)bh * S_ + q0) * S_;
    const float* Vbase = Vm + (size_t)b * S_ * D_ + h * KS_;

    float acc[4][4] = {};

    for (int kb = 0; kb < S_; kb += 16) {
        for (int i = tid; i < 64 * 16; i += 256) {
            int m  = i >> 4;
            int kk = i & 15;
            As[m][kk] = Arow[(size_t)m * S_ + kb + kk];
        }
        {
            int kk = tid >> 6;        // 0..3
            int n  = tid & 63;
            #pragma unroll
            for (int r = 0; r < 16; r += 4)
                Bs[kk + r][n] = Vbase[(size_t)(kb + kk + r) * D_ + n];
        }
        __syncthreads();

        #pragma unroll
        for (int kk = 0; kk < 16; kk++) {
            float ra[4], rb[4];
            #pragma unroll
            for (int i = 0; i < 4; i++) ra[i] = As[ty * 4 + i][kk];
            #pragma unroll
            for (int j = 0; j < 4; j++) rb[j] = Bs[kk][tx * 4 + j];
            #pragma unroll
            for (int i = 0; i < 4; i++)
                #pragma unroll
                for (int j = 0; j < 4; j++)
                    acc[i][j] = fmaf(ra[i], rb[j], acc[i][j]);
        }
        __syncthreads();
    }

    #pragma unroll
    for (int i = 0; i < 4; i++) {
        size_t q = q0 + ty * 4 + i;
        #pragma unroll
        for (int j = 0; j < 4; j++) {
            C[(size_t)b * S_ * D_ + q * D_ + h * KS_ + tx * 4 + j] = acc[i][j];
        }
    }
}

// ---------------------------------------------------------------------------
extern "C" void kernel_launch(void* const* d_in, const int* in_sizes, int n_in,
                              void* d_out, int out_size) {
    const float* q    = (const float*)d_in[0];
    const float* v    = (const float*)d_in[1];
    const float* mask = (const float*)d_in[2];
    const float* wq_w = (const float*)d_in[3];
    const float* wq_b = (const float*)d_in[4];
    const float* wk_w = (const float*)d_in[5];
    const float* wk_b = (const float*)d_in[6];
    const float* wv_w = (const float*)d_in[7];
    const float* wv_b = (const float*)d_in[8];
    const float* wo_w = (const float*)d_in[9];
    const float* wo_b = (const float*)d_in[10];

    float* out = (float*)d_out;
    float* heads = out;                         // [B,S,D]
    float* align = out + NTOK;                  // [B,H,S,S]

    float* scratch = nullptr;
    cudaGetSymbolAddress((void**)&scratch, g_scratch);
    float* Qm = scratch;
    float* Km = scratch + NTOK;
    float* Vm = scratch + 2 * NTOK;
    float* Cm = scratch + 3 * NTOK;

    dim3 thr(256);
    dim3 gproj(D_ / 128, (B_ * S_) / 128);      // (8, 32)

    gemm128<<<gproj, thr>>>(q, wq_w, wq_b, Qm, B_ * S_, D_, D_);
    gemm128<<<gproj, thr>>>(v, wk_w, wk_b, Km, B_ * S_, D_, D_);
    gemm128<<<gproj, thr>>>(v, wv_w, wv_b, Vm, B_ * S_, D_, D_);

    dim3 gsc(S_ / 64, S_ / 64, B_ * H_);        // (32, 32, 32)
    score_kernel<<<gsc, thr>>>(Qm, Km, mask, align);

    softmax_kernel<<<B_ * H_ * S_, thr>>>(align);

    dim3 gctx(S_ / 64, B_ * H_);                // (32, 32)
    context_kernel<<<gctx, thr>>>(align, Vm, Cm);

    gemm128<<<gproj, thr>>>(Cm, wo_w, wo_b, heads, B_ * S_, D_, D_);
}

// round 5
// speedup vs baseline: 1.2331x; 1.2331x over previous
#include <cuda_runtime.h>
#include <cuda_bf16.h>
#include <cstdint>

#define B_  2
#define S_  2048
#define D_  1024
#define H_  16
#define KS_ 64
#define NEG_BIG (-1.0e9f)

#define NTOK ((size_t)B_ * S_ * D_)   // 4,194,304 elements per [B,S,D] tensor

// ---------------------------------------------------------------------------
// Scratch layout (floats):
//  [0 .. 4*NTOK)  Qm, Km, Vm, Cm (fp32)
//  bf16 area: act hi/lo x2 streams + 4 transposed weight hi/lo pairs
// ---------------------------------------------------------------------------
#define F_ACT   (NTOK / 2)            // float slots per bf16 act array
#define F_W     ((size_t)D_ * D_ / 2) // float slots per bf16 weight array
__device__ __align__(16) float g_scratch[4 * NTOK + 4 * F_ACT + 8 * F_W];

// ============================ helpers ======================================
__device__ __forceinline__ uint32_t smem_u32(const void* p) {
    uint32_t a;
    asm("{ .reg .u64 t; cvta.to.shared.u64 t, %1; cvt.u32.u64 %0, t; }"
        : "=r"(a) : "l"(p));
    return a;
}
__device__ __forceinline__ void cp_async16(uint32_t saddr, const void* gaddr) {
    asm volatile("cp.async.cg.shared.global [%0], [%1], 16;"
                 :: "r"(saddr), "l"(gaddr) : "memory");
}
__device__ __forceinline__ void cp_commit() {
    asm volatile("cp.async.commit_group;" ::: "memory");
}
template <int N>
__device__ __forceinline__ void cp_wait() {
    asm volatile("cp.async.wait_group %0;" :: "n"(N) : "memory");
}

// mma.sync m16n8k16 row.col bf16 -> fp32, accumulate in place
__device__ __forceinline__ void mma16816(float* d, uint32_t a0, uint32_t a1,
                                         uint32_t a2, uint32_t a3,
                                         uint32_t b0, uint32_t b1) {
    asm volatile(
        "mma.sync.aligned.m16n8k16.row.col.f32.bf16.bf16.f32 "
        "{%0,%1,%2,%3}, {%4,%5,%6,%7}, {%8,%9}, {%0,%1,%2,%3};"
        : "+f"(d[0]), "+f"(d[1]), "+f"(d[2]), "+f"(d[3])
        : "r"(a0), "r"(a1), "r"(a2), "r"(a3), "r"(b0), "r"(b1));
}

// ======================= conversion kernels ================================
// fp32 -> bf16 hi/lo split (elementwise).  n must be multiple of 4.
__global__ void conv_act(const float* __restrict__ x,
                         __nv_bfloat16* __restrict__ h,
                         __nv_bfloat16* __restrict__ l, int n) {
    int i = blockIdx.x * blockDim.x + threadIdx.x;
    int i4 = i * 4;
    if (i4 >= n) return;
    float4 v = *(const float4*)(x + i4);
    float vs[4] = {v.x, v.y, v.z, v.w};
    __nv_bfloat16 hh[4], ll[4];
    #pragma unroll
    for (int j = 0; j < 4; j++) {
        __nv_bfloat16 hi = __float2bfloat16_rn(vs[j]);
        float r = vs[j] - __bfloat162float(hi);
        hh[j] = hi;
        ll[j] = __float2bfloat16_rn(r);
    }
    __nv_bfloat162* H2 = (__nv_bfloat162*)(h + i4);
    __nv_bfloat162* L2 = (__nv_bfloat162*)(l + i4);
    H2[0] = __nv_bfloat162(hh[0], hh[1]);
    H2[1] = __nv_bfloat162(hh[2], hh[3]);
    L2[0] = __nv_bfloat162(ll[0], ll[1]);
    L2[1] = __nv_bfloat162(ll[2], ll[3]);
}

// W[K,N] fp32 -> transposed Wt[N,K] bf16 hi/lo (B col-major for mma row.col)
__global__ void conv_w(const float* __restrict__ W,
                       __nv_bfloat16* __restrict__ Th,
                       __nv_bfloat16* __restrict__ Tl) {
    __shared__ float t[32][33];
    int n0 = blockIdx.x * 32, k0 = blockIdx.y * 32;
    int tx = threadIdx.x, ty = threadIdx.y;   // block (32,8)
    for (int r = ty; r < 32; r += 8)
        t[r][tx] = W[(size_t)(k0 + r) * D_ + n0 + tx];
    __syncthreads();
    for (int r = ty; r < 32; r += 8) {
        float x = t[tx][r];                   // = W[k0+tx][n0+r]
        __nv_bfloat16 hi = __float2bfloat16_rn(x);
        float res = x - __bfloat162float(hi);
        size_t o = (size_t)(n0 + r) * D_ + k0 + tx;
        Th[o] = hi;
        Tl[o] = __float2bfloat16_rn(res);
    }
}

// ======================= HMMA projection GEMM ==============================
// C[M,1024] = A[M,1024] @ W[1024,1024] + bias  via bf16x3.
// Block tile 128x128, BK=32, 8 warps (2x4), warp tile 64x32.
// smem: double-buffered {Ah, Al, Bh, Bl} tiles, row stride 80B (pad 16B).
#define GROW   80                       // bytes per smem row (32 bf16 + pad)
#define GTILE  (128 * GROW)             // 10240 B
#define GSTAGE (4 * GTILE)              // 40960 B
#define GSMEM  (2 * GSTAGE)             // 81920 B

__global__ void __launch_bounds__(256) gemm_mma(
    const __nv_bfloat16* __restrict__ Ah, const __nv_bfloat16* __restrict__ Al,
    const __nv_bfloat16* __restrict__ Bh, const __nv_bfloat16* __restrict__ Bl,
    const float* __restrict__ bias, float* __restrict__ C) {
    extern __shared__ char smem[];
    const uint32_t sb = smem_u32(smem);

    const int tid  = threadIdx.x;
    const int lane = tid & 31;
    const int wid  = tid >> 5;
    const int wm   = wid >> 2;           // 0..1
    const int wn   = wid & 3;            // 0..3
    const int g    = lane >> 2;          // 0..7
    const int q    = lane & 3;           // 0..3

    const int n0 = blockIdx.x * 128;
    const int m0 = blockIdx.y * 128;

    // gmem chunk mapping for cp.async: 512 16B-chunks per tile, 2 per thread
    const int cid0 = tid * 2;
    const int row0 = cid0 >> 2;
    const int cc0  = (cid0 & 3) * 8;     // element offset within 32-wide k
    const int row1 = (cid0 + 1) >> 2;
    const int cc1  = ((cid0 + 1) & 3) * 8;

    float acc[4][4][4] = {};

    const int NK = D_ / 32;              // 32 k-chunks

    // ---- prefetch stage 0
    {
        int k0 = 0;
        uint32_t s = sb;
        cp_async16(s + 0 * GTILE + row0 * GROW + (cc0 & 31) * 2, Ah + (size_t)(m0 + row0) * D_ + k0 + cc0);
        cp_async16(s + 0 * GTILE + row1 * GROW + (cc1 & 31) * 2, Ah + (size_t)(m0 + row1) * D_ + k0 + cc1);
        cp_async16(s + 1 * GTILE + row0 * GROW + (cc0 & 31) * 2, Al + (size_t)(m0 + row0) * D_ + k0 + cc0);
        cp_async16(s + 1 * GTILE + row1 * GROW + (cc1 & 31) * 2, Al + (size_t)(m0 + row1) * D_ + k0 + cc1);
        cp_async16(s + 2 * GTILE + row0 * GROW + (cc0 & 31) * 2, Bh + (size_t)(n0 + row0) * D_ + k0 + cc0);
        cp_async16(s + 2 * GTILE + row1 * GROW + (cc1 & 31) * 2, Bh + (size_t)(n0 + row1) * D_ + k0 + cc1);
        cp_async16(s + 3 * GTILE + row0 * GROW + (cc0 & 31) * 2, Bl + (size_t)(n0 + row0) * D_ + k0 + cc0);
        cp_async16(s + 3 * GTILE + row1 * GROW + (cc1 & 31) * 2, Bl + (size_t)(n0 + row1) * D_ + k0 + cc1);
        cp_commit();
    }

    for (int ks = 0; ks < NK; ks++) {
        if (ks + 1 < NK) {
            int k0 = (ks + 1) * 32;
            uint32_t s = sb + ((ks + 1) & 1) * GSTAGE;
            cp_async16(s + 0 * GTILE + row0 * GROW + (cc0 & 31) * 2, Ah + (size_t)(m0 + row0) * D_ + k0 + cc0);
            cp_async16(s + 0 * GTILE + row1 * GROW + (cc1 & 31) * 2, Ah + (size_t)(m0 + row1) * D_ + k0 + cc1);
            cp_async16(s + 1 * GTILE + row0 * GROW + (cc0 & 31) * 2, Al + (size_t)(m0 + row0) * D_ + k0 + cc0);
            cp_async16(s + 1 * GTILE + row1 * GROW + (cc1 & 31) * 2, Al + (size_t)(m0 + row1) * D_ + k0 + cc1);
            cp_async16(s + 2 * GTILE + row0 * GROW + (cc0 & 31) * 2, Bh + (size_t)(n0 + row0) * D_ + k0 + cc0);
            cp_async16(s + 2 * GTILE + row1 * GROW + (cc1 & 31) * 2, Bh + (size_t)(n0 + row1) * D_ + k0 + cc1);
            cp_async16(s + 3 * GTILE + row0 * GROW + (cc0 & 31) * 2, Bl + (size_t)(n0 + row0) * D_ + k0 + cc0);
            cp_async16(s + 3 * GTILE + row1 * GROW + (cc1 & 31) * 2, Bl + (size_t)(n0 + row1) * D_ + k0 + cc1);
            cp_commit();
            cp_wait<1>();
        } else {
            cp_wait<0>();
        }
        __syncthreads();

        const char* st  = smem + (ks & 1) * GSTAGE;
        const char* sAh = st;
        const char* sAl = st + GTILE;
        const char* sBh = st + 2 * GTILE;
        const char* sBl = st + 3 * GTILE;

        #pragma unroll
        for (int kk = 0; kk < 32; kk += 16) {
            // B fragments for this warp's 4 n-blocks
            uint32_t bh[4][2], bl[4][2];
            #pragma unroll
            for (int j = 0; j < 4; j++) {
                int n = wn * 32 + j * 8 + g;
                int o0 = n * GROW + (kk + 2 * q) * 2;
                int o1 = n * GROW + (kk + 2 * q + 8) * 2;
                bh[j][0] = *(const uint32_t*)(sBh + o0);
                bh[j][1] = *(const uint32_t*)(sBh + o1);
                bl[j][0] = *(const uint32_t*)(sBl + o0);
                bl[j][1] = *(const uint32_t*)(sBl + o1);
            }
            #pragma unroll
            for (int i = 0; i < 4; i++) {
                int m = wm * 64 + i * 16;
                int r0 = (m + g) * GROW;
                int r1 = (m + g + 8) * GROW;
                int c0 = (kk + 2 * q) * 2;
                int c1 = (kk + 2 * q + 8) * 2;
                uint32_t ah0 = *(const uint32_t*)(sAh + r0 + c0);
                uint32_t ah1 = *(const uint32_t*)(sAh + r1 + c0);
                uint32_t ah2 = *(const uint32_t*)(sAh + r0 + c1);
                uint32_t ah3 = *(const uint32_t*)(sAh + r1 + c1);
                uint32_t al0 = *(const uint32_t*)(sAl + r0 + c0);
                uint32_t al1 = *(const uint32_t*)(sAl + r1 + c0);
                uint32_t al2 = *(const uint32_t*)(sAl + r0 + c1);
                uint32_t al3 = *(const uint32_t*)(sAl + r1 + c1);
                #pragma unroll
                for (int j = 0; j < 4; j++) {
                    mma16816(acc[i][j], ah0, ah1, ah2, ah3, bh[j][0], bh[j][1]);
                    mma16816(acc[i][j], ah0, ah1, ah2, ah3, bl[j][0], bl[j][1]);
                    mma16816(acc[i][j], al0, al1, al2, al3, bh[j][0], bh[j][1]);
                }
            }
        }
        __syncthreads();
    }

    // ---- epilogue
    #pragma unroll
    for (int i = 0; i < 4; i++) {
        int row = m0 + wm * 64 + i * 16;
        #pragma unroll
        for (int j = 0; j < 4; j++) {
            int col = n0 + wn * 32 + j * 8 + 2 * q;
            float b0 = __ldg(bias + col);
            float b1 = __ldg(bias + col + 1);
            float2 v0 = make_float2(acc[i][j][0] + b0, acc[i][j][1] + b1);
            float2 v1 = make_float2(acc[i][j][2] + b0, acc[i][j][3] + b1);
            *(float2*)&C[(size_t)(row + g) * D_ + col]     = v0;
            *(float2*)&C[(size_t)(row + g + 8) * D_ + col] = v1;
        }
    }
}

// ======================= attention (unchanged from R1) =====================
__global__ void score_kernel(const float* __restrict__ Q, const float* __restrict__ Kmat,
                             const float* __restrict__ mask, float* __restrict__ out) {
    __shared__ float Qs[64][65];
    __shared__ float Ks[64][65];

    int bh = blockIdx.z;
    int b  = bh >> 4;
    int h  = bh & 15;
    int q0 = blockIdx.y * 64;
    int k0 = blockIdx.x * 64;
    int tid = threadIdx.x;

    const float* Qbase = Q    + ((size_t)b * S_ + q0) * D_ + h * KS_;
    const float* Kbase = Kmat + ((size_t)b * S_ + k0) * D_ + h * KS_;

    for (int i = tid; i < 64 * 16; i += 256) {
        int r  = i >> 4;
        int c4 = (i & 15) << 2;
        float4 qv = *(const float4*)(Qbase + (size_t)r * D_ + c4);
        Qs[r][c4 + 0] = qv.x; Qs[r][c4 + 1] = qv.y;
        Qs[r][c4 + 2] = qv.z; Qs[r][c4 + 3] = qv.w;
        float4 kv = *(const float4*)(Kbase + (size_t)r * D_ + c4);
        Ks[r][c4 + 0] = kv.x; Ks[r][c4 + 1] = kv.y;
        Ks[r][c4 + 2] = kv.z; Ks[r][c4 + 3] = kv.w;
    }
    __syncthreads();

    int tx = tid & 15;
    int ty = tid >> 4;
    float acc[4][4] = {};

    #pragma unroll
    for (int d = 0; d < 64; d++) {
        float ra[4], rb[4];
        #pragma unroll
        for (int i = 0; i < 4; i++) ra[i] = Qs[ty * 4 + i][d];
        #pragma unroll
        for (int j = 0; j < 4; j++) rb[j] = Ks[tx * 4 + j][d];
        #pragma unroll
        for (int i = 0; i < 4; i++)
            #pragma unroll
            for (int j = 0; j < 4; j++)
                acc[i][j] = fmaf(ra[i], rb[j], acc[i][j]);
    }

    const float* mrow = mask + (size_t)b * S_ * S_;
    float* orow = out + (size_t)bh * S_ * S_;
    #pragma unroll
    for (int i = 0; i < 4; i++) {
        int qg = q0 + ty * 4 + i;
        #pragma unroll
        for (int j = 0; j < 4; j++) {
            int kg = k0 + tx * 4 + j;
            float s = acc[i][j] * 0.125f;
            s *= mrow[(size_t)qg * S_ + kg];
            if (s == 0.0f) s = NEG_BIG;
            orow[(size_t)qg * S_ + kg] = s;
        }
    }
}

__global__ void softmax_kernel(float* __restrict__ a) {
    __shared__ float buf[S_];
    __shared__ float red[8];

    size_t row = blockIdx.x;
    float* p = a + row * S_;
    int tid = threadIdx.x;

    float mx = -3.402823466e38f;
    for (int i = tid; i < S_; i += 256) {
        float v = p[i];
        buf[i] = v;
        mx = fmaxf(mx, v);
    }
    #pragma unroll
    for (int o = 16; o > 0; o >>= 1) mx = fmaxf(mx, __shfl_xor_sync(0xffffffffu, mx, o));
    if ((tid & 31) == 0) red[tid >> 5] = mx;
    __syncthreads();
    float bmx = red[0];
    #pragma unroll
    for (int i = 1; i < 8; i++) bmx = fmaxf(bmx, red[i]);
    __syncthreads();

    float sm = 0.0f;
    for (int i = tid; i < S_; i += 256) {
        float e = expf(buf[i] - bmx);
        buf[i] = e;
        sm += e;
    }
    #pragma unroll
    for (int o = 16; o > 0; o >>= 1) sm += __shfl_xor_sync(0xffffffffu, sm, o);
    if ((tid & 31) == 0) red[tid >> 5] = sm;
    __syncthreads();
    float tot = 0.0f;
    #pragma unroll
    for (int i = 0; i < 8; i++) tot += red[i];
    float inv = 1.0f / tot;

    for (int i = tid; i < S_; i += 256) p[i] = buf[i] * inv;
}

__global__ void context_kernel(const float* __restrict__ A, const float* __restrict__ Vm,
                               float* __restrict__ C) {
    __shared__ float As[64][17];
    __shared__ float Bs[16][64];

    int bh = blockIdx.y;
    int b  = bh >> 4;
    int h  = bh & 15;
    int q0 = blockIdx.x * 64;
    int tid = threadIdx.x;
    int tx = tid & 15;
    int ty = tid >> 4;

    const float* Arow  = A  + ((size_t)bh * S_ + q0) * S_;
    const float* Vbase = Vm + (size_t)b * S_ * D_ + h * KS_;

    float acc[4][4] = {};

    for (int kb = 0; kb < S_; kb += 16) {
        for (int i = tid; i < 64 * 16; i += 256) {
            int m  = i >> 4;
            int kk = i & 15;
            As[m][kk] = Arow[(size_t)m * S_ + kb + kk];
        }
        {
            int kk = tid >> 6;
            int n  = tid & 63;
            #pragma unroll
            for (int r = 0; r < 16; r += 4)
                Bs[kk + r][n] = Vbase[(size_t)(kb + kk + r) * D_ + n];
        }
        __syncthreads();

        #pragma unroll
        for (int kk = 0; kk < 16; kk++) {
            float ra[4], rb[4];
            #pragma unroll
            for (int i = 0; i < 4; i++) ra[i] = As[ty * 4 + i][kk];
            #pragma unroll
            for (int j = 0; j < 4; j++) rb[j] = Bs[kk][tx * 4 + j];
            #pragma unroll
            for (int i = 0; i < 4; i++)
                #pragma unroll
                for (int j = 0; j < 4; j++)
                    acc[i][j] = fmaf(ra[i], rb[j], acc[i][j]);
        }
        __syncthreads();
    }

    #pragma unroll
    for (int i = 0; i < 4; i++) {
        size_t q = q0 + ty * 4 + i;
        #pragma unroll
        for (int j = 0; j < 4; j++) {
            C[(size_t)b * S_ * D_ + q * D_ + h * KS_ + tx * 4 + j] = acc[i][j];
        }
    }
}

// ---------------------------------------------------------------------------
extern "C" void kernel_launch(void* const* d_in, const int* in_sizes, int n_in,
                              void* d_out, int out_size) {
    const float* q    = (const float*)d_in[0];
    const float* v    = (const float*)d_in[1];
    const float* mask = (const float*)d_in[2];
    const float* wq_w = (const float*)d_in[3];
    const float* wq_b = (const float*)d_in[4];
    const float* wk_w = (const float*)d_in[5];
    const float* wk_b = (const float*)d_in[6];
    const float* wv_w = (const float*)d_in[7];
    const float* wv_b = (const float*)d_in[8];
    const float* wo_w = (const float*)d_in[9];
    const float* wo_b = (const float*)d_in[10];

    float* out = (float*)d_out;
    float* heads = out;                         // [B,S,D]
    float* align = out + NTOK;                  // [B,H,S,S]

    float* scratch = nullptr;
    cudaGetSymbolAddress((void**)&scratch, g_scratch);
    float* Qm = scratch;
    float* Km = scratch + NTOK;
    float* Vm = scratch + 2 * NTOK;
    float* Cm = scratch + 3 * NTOK;

    float* fb = scratch + 4 * NTOK;             // bf16 area base (float slots)
    __nv_bfloat16* AqH = (__nv_bfloat16*)(fb);
    __nv_bfloat16* AqL = (__nv_bfloat16*)(fb + F_ACT);
    __nv_bfloat16* AvH = (__nv_bfloat16*)(fb + 2 * F_ACT);
    __nv_bfloat16* AvL = (__nv_bfloat16*)(fb + 3 * F_ACT);
    float* wb = fb + 4 * F_ACT;
    __nv_bfloat16* WqH = (__nv_bfloat16*)(wb + 0 * F_W);
    __nv_bfloat16* WqL = (__nv_bfloat16*)(wb + 1 * F_W);
    __nv_bfloat16* WkH = (__nv_bfloat16*)(wb + 2 * F_W);
    __nv_bfloat16* WkL = (__nv_bfloat16*)(wb + 3 * F_W);
    __nv_bfloat16* WvH = (__nv_bfloat16*)(wb + 4 * F_W);
    __nv_bfloat16* WvL = (__nv_bfloat16*)(wb + 5 * F_W);
    __nv_bfloat16* WoH = (__nv_bfloat16*)(wb + 6 * F_W);
    __nv_bfloat16* WoL = (__nv_bfloat16*)(wb + 7 * F_W);

    cudaFuncSetAttribute(gemm_mma, cudaFuncAttributeMaxDynamicSharedMemorySize, GSMEM);

    dim3 thr(256);
    dim3 gconvW(32, 32);
    dim3 bconvW(32, 8);
    int nAct = (int)NTOK;
    int gA = (nAct / 4 + 255) / 256;

    // Weight + activation conversions
    conv_w<<<gconvW, bconvW>>>(wq_w, WqH, WqL);
    conv_w<<<gconvW, bconvW>>>(wk_w, WkH, WkL);
    conv_w<<<gconvW, bconvW>>>(wv_w, WvH, WvL);
    conv_w<<<gconvW, bconvW>>>(wo_w, WoH, WoL);
    conv_act<<<gA, 256>>>(q, AqH, AqL, nAct);
    conv_act<<<gA, 256>>>(v, AvH, AvL, nAct);

    // Projections on tensor cores (bf16x3 via mma.sync)
    dim3 gproj(D_ / 128, (B_ * S_) / 128);      // (8, 32)
    gemm_mma<<<gproj, 256, GSMEM>>>(AqH, AqL, WqH, WqL, wq_b, Qm);
    gemm_mma<<<gproj, 256, GSMEM>>>(AvH, AvL, WkH, WkL, wk_b, Km);
    gemm_mma<<<gproj, 256, GSMEM>>>(AvH, AvL, WvH, WvL, wv_b, Vm);

    // Attention
    dim3 gsc(S_ / 64, S_ / 64, B_ * H_);        // (32, 32, 32)
    score_kernel<<<gsc, thr>>>(Qm, Km, mask, align);
    softmax_kernel<<<B_ * H_ * S_, thr>>>(align);
    dim3 gctx(S_ / 64, B_ * H_);                // (32, 32)
    context_kernel<<<gctx, thr>>>(align, Vm, Cm);

    // Output projection
    conv_act<<<gA, 256>>>(Cm, AqH, AqL, nAct);
    gemm_mma<<<gproj, 256, GSMEM>>>(AqH, AqL, WoH, WoL, wo_b, heads);
}

// round 6
// speedup vs baseline: 1.4373x; 1.1656x over previous
#include <cuda_runtime.h>
#include <cuda_bf16.h>
#include <cstdint>

#define B_  2
#define S_  2048
#define D_  1024
#define H_  16
#define KS_ 64
#define NEG_BIG (-1.0e9f)

#define NTOK ((size_t)B_ * S_ * D_)

#define F_ACT   (NTOK / 2)
#define F_W     ((size_t)D_ * D_ / 2)
__device__ __align__(16) float g_scratch[4 * NTOK + 4 * F_ACT + 8 * F_W];

typedef uint32_t u32;

// ============================ helpers ======================================
__device__ __forceinline__ u32 smem_u32(const void* p) {
    u32 a;
    asm("{ .reg .u64 t; cvta.to.shared.u64 t, %1; cvt.u32.u64 %0, t; }"
        : "=r"(a) : "l"(p));
    return a;
}
__device__ __forceinline__ void cp_async16(u32 saddr, const void* gaddr) {
    asm volatile("cp.async.cg.shared.global [%0], [%1], 16;"
                 :: "r"(saddr), "l"(gaddr) : "memory");
}
__device__ __forceinline__ void cp_commit() {
    asm volatile("cp.async.commit_group;" ::: "memory");
}
template <int N>
__device__ __forceinline__ void cp_wait() {
    asm volatile("cp.async.wait_group %0;" :: "n"(N) : "memory");
}
__device__ __forceinline__ void mma16816(float* d, u32 a0, u32 a1,
                                         u32 a2, u32 a3, u32 b0, u32 b1) {
    asm volatile(
        "mma.sync.aligned.m16n8k16.row.col.f32.bf16.bf16.f32 "
        "{%0,%1,%2,%3}, {%4,%5,%6,%7}, {%8,%9}, {%0,%1,%2,%3};"
        : "+f"(d[0]), "+f"(d[1]), "+f"(d[2]), "+f"(d[3])
        : "r"(a0), "r"(a1), "r"(a2), "r"(a3), "r"(b0), "r"(b1));
}
__device__ __forceinline__ u32 prmt(u32 a, u32 b, u32 s) {
    u32 d; asm("prmt.b32 %0,%1,%2,%3;" : "=r"(d) : "r"(a), "r"(b), "r"(s));
    return d;
}
__device__ __forceinline__ void ldsm_x2_t(u32& r0, u32& r1, u32 a) {
    asm volatile("ldmatrix.sync.aligned.m8n8.x2.trans.shared.b16 {%0,%1}, [%2];"
                 : "=r"(r0), "=r"(r1) : "r"(a));
}
// round-to-nearest-even fp32 -> bf16 bits (pure ALU)
__device__ __forceinline__ u32 f2bf_bits(float x) {
    u32 u = __float_as_uint(x);
    return (u + 0x7FFFu + ((u >> 16) & 1u)) >> 16;
}
// FMA-pipe exp (avoids MUFU EX2 bottleneck). x <= 0 here; clamp for -1e9.
__device__ __forceinline__ float exp_fast(float x) {
    x = fmaxf(x, -87.3f);
    float y = x * 1.44269504089f;
    float n = rintf(y);
    float f = y - n;
    float p = 1.33336498402e-3f;
    p = fmaf(p, f, 9.61793571616e-3f);
    p = fmaf(p, f, 5.55043442248e-2f);
    p = fmaf(p, f, 2.40226506959e-1f);
    p = fmaf(p, f, 6.93147180560e-1f);
    p = fmaf(p, f, 1.0f);
    return __int_as_float(__float_as_int(p) + (((int)n) << 23));
}

// ======================= conversion kernels ================================
__global__ void conv_act(const float* __restrict__ x,
                         __nv_bfloat16* __restrict__ h,
                         __nv_bfloat16* __restrict__ l, int n) {
    int i = blockIdx.x * blockDim.x + threadIdx.x;
    int i4 = i * 4;
    if (i4 >= n) return;
    float4 v = *(const float4*)(x + i4);
    float vs[4] = {v.x, v.y, v.z, v.w};
    __nv_bfloat16 hh[4], ll[4];
    #pragma unroll
    for (int j = 0; j < 4; j++) {
        __nv_bfloat16 hi = __float2bfloat16_rn(vs[j]);
        float r = vs[j] - __bfloat162float(hi);
        hh[j] = hi;
        ll[j] = __float2bfloat16_rn(r);
    }
    __nv_bfloat162* H2 = (__nv_bfloat162*)(h + i4);
    __nv_bfloat162* L2 = (__nv_bfloat162*)(l + i4);
    H2[0] = __nv_bfloat162(hh[0], hh[1]);
    H2[1] = __nv_bfloat162(hh[2], hh[3]);
    L2[0] = __nv_bfloat162(ll[0], ll[1]);
    L2[1] = __nv_bfloat162(ll[2], ll[3]);
}

__global__ void conv_w(const float* __restrict__ W,
                       __nv_bfloat16* __restrict__ Th,
                       __nv_bfloat16* __restrict__ Tl) {
    __shared__ float t[32][33];
    int n0 = blockIdx.x * 32, k0 = blockIdx.y * 32;
    int tx = threadIdx.x, ty = threadIdx.y;
    for (int r = ty; r < 32; r += 8)
        t[r][tx] = W[(size_t)(k0 + r) * D_ + n0 + tx];
    __syncthreads();
    for (int r = ty; r < 32; r += 8) {
        float x = t[tx][r];
        __nv_bfloat16 hi = __float2bfloat16_rn(x);
        float res = x - __bfloat162float(hi);
        size_t o = (size_t)(n0 + r) * D_ + k0 + tx;
        Th[o] = hi;
        Tl[o] = __float2bfloat16_rn(res);
    }
}

// ======================= HMMA projection GEMM (unchanged, R5-verified) =====
#define GROW   80
#define GTILE  (128 * GROW)
#define GSTAGE (4 * GTILE)
#define GSMEM  (2 * GSTAGE)

__global__ void __launch_bounds__(256) gemm_mma(
    const __nv_bfloat16* __restrict__ Ah, const __nv_bfloat16* __restrict__ Al,
    const __nv_bfloat16* __restrict__ Bh, const __nv_bfloat16* __restrict__ Bl,
    const float* __restrict__ bias, float* __restrict__ C) {
    extern __shared__ char smem[];
    const u32 sb = smem_u32(smem);

    const int tid  = threadIdx.x;
    const int lane = tid & 31;
    const int wid  = tid >> 5;
    const int wm   = wid >> 2;
    const int wn   = wid & 3;
    const int g    = lane >> 2;
    const int q    = lane & 3;

    const int n0 = blockIdx.x * 128;
    const int m0 = blockIdx.y * 128;

    const int cid0 = tid * 2;
    const int row0 = cid0 >> 2;
    const int cc0  = (cid0 & 3) * 8;
    const int row1 = (cid0 + 1) >> 2;
    const int cc1  = ((cid0 + 1) & 3) * 8;

    float acc[4][4][4] = {};
    const int NK = D_ / 32;

    {
        int k0 = 0;
        u32 s = sb;
        cp_async16(s + 0 * GTILE + row0 * GROW + (cc0 & 31) * 2, Ah + (size_t)(m0 + row0) * D_ + k0 + cc0);
        cp_async16(s + 0 * GTILE + row1 * GROW + (cc1 & 31) * 2, Ah + (size_t)(m0 + row1) * D_ + k0 + cc1);
        cp_async16(s + 1 * GTILE + row0 * GROW + (cc0 & 31) * 2, Al + (size_t)(m0 + row0) * D_ + k0 + cc0);
        cp_async16(s + 1 * GTILE + row1 * GROW + (cc1 & 31) * 2, Al + (size_t)(m0 + row1) * D_ + k0 + cc1);
        cp_async16(s + 2 * GTILE + row0 * GROW + (cc0 & 31) * 2, Bh + (size_t)(n0 + row0) * D_ + k0 + cc0);
        cp_async16(s + 2 * GTILE + row1 * GROW + (cc1 & 31) * 2, Bh + (size_t)(n0 + row1) * D_ + k0 + cc1);
        cp_async16(s + 3 * GTILE + row0 * GROW + (cc0 & 31) * 2, Bl + (size_t)(n0 + row0) * D_ + k0 + cc0);
        cp_async16(s + 3 * GTILE + row1 * GROW + (cc1 & 31) * 2, Bl + (size_t)(n0 + row1) * D_ + k0 + cc1);
        cp_commit();
    }

    for (int ks = 0; ks < NK; ks++) {
        if (ks + 1 < NK) {
            int k0 = (ks + 1) * 32;
            u32 s = sb + ((ks + 1) & 1) * GSTAGE;
            cp_async16(s + 0 * GTILE + row0 * GROW + (cc0 & 31) * 2, Ah + (size_t)(m0 + row0) * D_ + k0 + cc0);
            cp_async16(s + 0 * GTILE + row1 * GROW + (cc1 & 31) * 2, Ah + (size_t)(m0 + row1) * D_ + k0 + cc1);
            cp_async16(s + 1 * GTILE + row0 * GROW + (cc0 & 31) * 2, Al + (size_t)(m0 + row0) * D_ + k0 + cc0);
            cp_async16(s + 1 * GTILE + row1 * GROW + (cc1 & 31) * 2, Al + (size_t)(m0 + row1) * D_ + k0 + cc1);
            cp_async16(s + 2 * GTILE + row0 * GROW + (cc0 & 31) * 2, Bh + (size_t)(n0 + row0) * D_ + k0 + cc0);
            cp_async16(s + 2 * GTILE + row1 * GROW + (cc1 & 31) * 2, Bh + (size_t)(n0 + row1) * D_ + k0 + cc1);
            cp_async16(s + 3 * GTILE + row0 * GROW + (cc0 & 31) * 2, Bl + (size_t)(n0 + row0) * D_ + k0 + cc0);
            cp_async16(s + 3 * GTILE + row1 * GROW + (cc1 & 31) * 2, Bl + (size_t)(n0 + row1) * D_ + k0 + cc1);
            cp_commit();
            cp_wait<1>();
        } else {
            cp_wait<0>();
        }
        __syncthreads();

        const char* st  = smem + (ks & 1) * GSTAGE;
        const char* sAh = st;
        const char* sAl = st + GTILE;
        const char* sBh = st + 2 * GTILE;
        const char* sBl = st + 3 * GTILE;

        #pragma unroll
        for (int kk = 0; kk < 32; kk += 16) {
            u32 bh[4][2], bl[4][2];
            #pragma unroll
            for (int j = 0; j < 4; j++) {
                int n = wn * 32 + j * 8 + g;
                int o0 = n * GROW + (kk + 2 * q) * 2;
                int o1 = n * GROW + (kk + 2 * q + 8) * 2;
                bh[j][0] = *(const u32*)(sBh + o0);
                bh[j][1] = *(const u32*)(sBh + o1);
                bl[j][0] = *(const u32*)(sBl + o0);
                bl[j][1] = *(const u32*)(sBl + o1);
            }
            #pragma unroll
            for (int i = 0; i < 4; i++) {
                int m = wm * 64 + i * 16;
                int r0 = (m + g) * GROW;
                int r1 = (m + g + 8) * GROW;
                int c0 = (kk + 2 * q) * 2;
                int c1 = (kk + 2 * q + 8) * 2;
                u32 ah0 = *(const u32*)(sAh + r0 + c0);
                u32 ah1 = *(const u32*)(sAh + r1 + c0);
                u32 ah2 = *(const u32*)(sAh + r0 + c1);
                u32 ah3 = *(const u32*)(sAh + r1 + c1);
                u32 al0 = *(const u32*)(sAl + r0 + c0);
                u32 al1 = *(const u32*)(sAl + r1 + c0);
                u32 al2 = *(const u32*)(sAl + r0 + c1);
                u32 al3 = *(const u32*)(sAl + r1 + c1);
                #pragma unroll
                for (int j = 0; j < 4; j++) {
                    mma16816(acc[i][j], ah0, ah1, ah2, ah3, bh[j][0], bh[j][1]);
                    mma16816(acc[i][j], ah0, ah1, ah2, ah3, bl[j][0], bl[j][1]);
                    mma16816(acc[i][j], al0, al1, al2, al3, bh[j][0], bh[j][1]);
                }
            }
        }
        __syncthreads();
    }

    #pragma unroll
    for (int i = 0; i < 4; i++) {
        int row = m0 + wm * 64 + i * 16;
        #pragma unroll
        for (int j = 0; j < 4; j++) {
            int col = n0 + wn * 32 + j * 8 + 2 * q;
            float b0 = __ldg(bias + col);
            float b1 = __ldg(bias + col + 1);
            float2 v0 = make_float2(acc[i][j][0] + b0, acc[i][j][1] + b1);
            float2 v1 = make_float2(acc[i][j][2] + b0, acc[i][j][3] + b1);
            *(float2*)&C[(size_t)(row + g) * D_ + col]     = v0;
            *(float2*)&C[(size_t)(row + g + 8) * D_ + col] = v1;
        }
    }
}

// ======================= fused attention ===================================
// One block: 16 q-rows x full 2048 k for one (b,h).
// Phase 1: scores = (Qbf16x3 . K)/8 * mask (zeros -> -1e9) into smem fp32.
// Phase 2: softmax in smem (FMA-pipe exp), write probs to align (fp32),
//          pack bf16 hi/lo of prob into same smem slots.
// Phase 3: O = P . V via bf16x3 mma (V staged+split from fp32, ldmatrix.trans).
#define RQ 16
#define CK 128
#define SROW 2056                          // fp32 words per score row (pad)
#define SC_BYTES (RQ * SROW * 4)           // 131584
#define KROW 144                           // 64 bf16 + 16B pad
#define KTILE (CK * KROW)                  // 18432
#define KSTG  (2 * KTILE)                  // 36864 (hi+lo)
#define KA_OFF SC_BYTES
#define Q_OFF (KA_OFF + 2 * KSTG)          // 205312
#define QTILE (RQ * KROW)                  // 2304
#define FA_SMEM (Q_OFF + 2 * QTILE)        // 209920

__device__ __forceinline__ void stage_k_chunk(
    u32 sb, const __nv_bfloat16* Kh, const __nv_bfloat16* Kl,
    int b, int h, int c, int buf, int tid) {
    #pragma unroll
    for (int i = tid; i < 2048; i += 256) {
        int which = i >> 10, j = i & 1023, row = j >> 3, sub = j & 7;
        const __nv_bfloat16* src = (which ? Kl : Kh) +
            ((size_t)b * S_ + (size_t)c * CK + row) * D_ + h * KS_ + sub * 8;
        cp_async16(sb + KA_OFF + buf * KSTG + which * KTILE + row * KROW + sub * 16, src);
    }
}

__global__ void __launch_bounds__(256) fused_attn(
    const __nv_bfloat16* __restrict__ Qh, const __nv_bfloat16* __restrict__ Ql,
    const __nv_bfloat16* __restrict__ Kh, const __nv_bfloat16* __restrict__ Kl,
    const float* __restrict__ Vm, const float* __restrict__ mask,
    float* __restrict__ align, float* __restrict__ Cm) {
    extern __shared__ char smem[];
    const u32 sb = smem_u32(smem);
    float* sc = (float*)smem;
    u32* scu = (u32*)smem;

    const int tid = threadIdx.x, lane = tid & 31, w = tid >> 5;
    const int g = lane >> 2, qq = lane & 3;
    const int bh = blockIdx.y, b = bh >> 4, h = bh & 15;
    const int q0 = blockIdx.x * RQ;

    // ---- stage Q (exactly 256 cp.async: 2 arrays x 16 rows x 8 subs) ----
    {
        int which = tid >> 7, j = tid & 127, row = j >> 3, sub = j & 7;
        const __nv_bfloat16* src = (which ? Ql : Qh) +
            ((size_t)b * S_ + q0 + row) * D_ + h * KS_ + sub * 8;
        cp_async16(sb + Q_OFF + which * QTILE + row * KROW + sub * 16, src);
    }
    stage_k_chunk(sb, Kh, Kl, b, h, 0, 0, tid);
    cp_commit();

    u32 ah[4][4], al[4][4];
    const float* mrow = mask + (size_t)b * S_ * S_;

    // =================== phase 1: scores ===================
    for (int c = 0; c < 16; c++) {
        if (c + 1 < 16) {
            stage_k_chunk(sb, Kh, Kl, b, h, c + 1, (c + 1) & 1, tid);
            cp_commit();
            cp_wait<1>();
        } else {
            cp_wait<0>();
        }
        __syncthreads();

        if (c == 0) {
            const char* sQh = smem + Q_OFF;
            const char* sQl = smem + Q_OFF + QTILE;
            #pragma unroll
            for (int ks = 0; ks < 4; ks++) {
                int c0 = (ks * 16 + 2 * qq) * 2, c1 = c0 + 16;
                ah[ks][0] = *(const u32*)(sQh + g * KROW + c0);
                ah[ks][1] = *(const u32*)(sQh + (g + 8) * KROW + c0);
                ah[ks][2] = *(const u32*)(sQh + g * KROW + c1);
                ah[ks][3] = *(const u32*)(sQh + (g + 8) * KROW + c1);
                al[ks][0] = *(const u32*)(sQl + g * KROW + c0);
                al[ks][1] = *(const u32*)(sQl + (g + 8) * KROW + c0);
                al[ks][2] = *(const u32*)(sQl + g * KROW + c1);
                al[ks][3] = *(const u32*)(sQl + (g + 8) * KROW + c1);
            }
        }

        const char* sKh = smem + KA_OFF + (c & 1) * KSTG;
        const char* sKl = sKh + KTILE;

        #pragma unroll
        for (int nb = 0; nb < 2; nb++) {
            float acc[4] = {0.f, 0.f, 0.f, 0.f};
            int nbase = w * 16 + nb * 8;
            #pragma unroll
            for (int ks = 0; ks < 4; ks++) {
                int ko = (ks * 16 + 2 * qq) * 2;
                u32 bh0 = *(const u32*)(sKh + (nbase + g) * KROW + ko);
                u32 bh1 = *(const u32*)(sKh + (nbase + g) * KROW + ko + 16);
                u32 bl0 = *(const u32*)(sKl + (nbase + g) * KROW + ko);
                u32 bl1 = *(const u32*)(sKl + (nbase + g) * KROW + ko + 16);
                mma16816(acc, ah[ks][0], ah[ks][1], ah[ks][2], ah[ks][3], bh0, bh1);
                mma16816(acc, ah[ks][0], ah[ks][1], ah[ks][2], ah[ks][3], bl0, bl1);
                mma16816(acc, al[ks][0], al[ks][1], al[ks][2], al[ks][3], bh0, bh1);
            }
            int col = c * 128 + nbase + 2 * qq;
            int r0 = q0 + g, r1 = q0 + g + 8;
            float2 m0 = *(const float2*)&mrow[(size_t)r0 * S_ + col];
            float2 m1 = *(const float2*)&mrow[(size_t)r1 * S_ + col];
            float s0 = acc[0] * 0.125f * m0.x; if (s0 == 0.0f) s0 = NEG_BIG;
            float s1 = acc[1] * 0.125f * m0.y; if (s1 == 0.0f) s1 = NEG_BIG;
            float s2 = acc[2] * 0.125f * m1.x; if (s2 == 0.0f) s2 = NEG_BIG;
            float s3 = acc[3] * 0.125f * m1.y; if (s3 == 0.0f) s3 = NEG_BIG;
            *(float2*)&sc[g * SROW + col]       = make_float2(s0, s1);
            *(float2*)&sc[(g + 8) * SROW + col] = make_float2(s2, s3);
        }
        __syncthreads();
    }

    // =================== phase 2: softmax ===================
    #pragma unroll
    for (int rr = 0; rr < 2; rr++) {
        int r = w * 2 + rr;
        float* row = sc + r * SROW;
        float mx = -3.402823466e38f;
        for (int i = lane; i < S_; i += 32) mx = fmaxf(mx, row[i]);
        #pragma unroll
        for (int o = 16; o > 0; o >>= 1) mx = fmaxf(mx, __shfl_xor_sync(0xffffffffu, mx, o));
        float sm = 0.f;
        for (int i = lane; i < S_; i += 32) {
            float e = exp_fast(row[i] - mx);
            row[i] = e;
            sm += e;
        }
        #pragma unroll
        for (int o = 16; o > 0; o >>= 1) sm += __shfl_xor_sync(0xffffffffu, sm, o);
        float inv = 1.0f / sm;
        float* arow = align + ((size_t)bh * S_ + q0 + r) * S_;
        u32* prow = (u32*)row;
        for (int i = lane; i < S_; i += 32) {
            float p = row[i] * inv;
            arow[i] = p;
            u32 hb = f2bf_bits(p);
            float res = p - __uint_as_float(hb << 16);
            u32 lb = f2bf_bits(res);
            prow[i] = hb | (lb << 16);
        }
    }
    __syncthreads();

    // =================== phase 3: context O = P.V ===================
    float oacc[4] = {0.f, 0.f, 0.f, 0.f};
    for (int c = 0; c < 16; c++) {
        // stage V chunk c (fp32 -> bf16 hi/lo split) into buffer c&1
        {
            const float* vsrc = Vm + ((size_t)b * S_ + (size_t)c * CK) * D_ + h * KS_;
            char* dVh = smem + KA_OFF + (c & 1) * KSTG;
            char* dVl = dVh + KTILE;
            #pragma unroll
            for (int i = tid * 4; i < CK * 64; i += 1024) {
                int k = i >> 6, n = i & 63;
                float4 vv = *(const float4*)(vsrc + (size_t)k * D_ + n);
                u32 hx = f2bf_bits(vv.x), hy = f2bf_bits(vv.y);
                u32 hz = f2bf_bits(vv.z), hw = f2bf_bits(vv.w);
                u32 lx = f2bf_bits(vv.x - __uint_as_float(hx << 16));
                u32 ly = f2bf_bits(vv.y - __uint_as_float(hy << 16));
                u32 lz = f2bf_bits(vv.z - __uint_as_float(hz << 16));
                u32 lw = f2bf_bits(vv.w - __uint_as_float(hw << 16));
                *(u32*)(dVh + k * KROW + n * 2)     = hx | (hy << 16);
                *(u32*)(dVh + k * KROW + n * 2 + 4) = hz | (hw << 16);
                *(u32*)(dVl + k * KROW + n * 2)     = lx | (ly << 16);
                *(u32*)(dVl + k * KROW + n * 2 + 4) = lz | (lw << 16);
            }
        }
        __syncthreads();

        u32 vbase = sb + KA_OFF + (c & 1) * KSTG;
        #pragma unroll
        for (int ks = 0; ks < 8; ks++) {
            int k0 = c * 128 + ks * 16 + 2 * qq;
            uint2 w0 = *(const uint2*)&scu[g * SROW + k0];
            uint2 w1 = *(const uint2*)&scu[g * SROW + k0 + 8];
            uint2 w2 = *(const uint2*)&scu[(g + 8) * SROW + k0];
            uint2 w3 = *(const uint2*)&scu[(g + 8) * SROW + k0 + 8];
            u32 pah0 = prmt(w0.x, w0.y, 0x5410), pal0 = prmt(w0.x, w0.y, 0x7632);
            u32 pah1 = prmt(w2.x, w2.y, 0x5410), pal1 = prmt(w2.x, w2.y, 0x7632);
            u32 pah2 = prmt(w1.x, w1.y, 0x5410), pal2 = prmt(w1.x, w1.y, 0x7632);
            u32 pah3 = prmt(w3.x, w3.y, 0x5410), pal3 = prmt(w3.x, w3.y, 0x7632);

            u32 addr = vbase + (ks * 16 + (lane & 15)) * KROW + w * 16;
            u32 vbh0, vbh1, vbl0, vbl1;
            ldsm_x2_t(vbh0, vbh1, addr);
            ldsm_x2_t(vbl0, vbl1, addr + KTILE);

            mma16816(oacc, pah0, pah1, pah2, pah3, vbh0, vbh1);
            mma16816(oacc, pah0, pah1, pah2, pah3, vbl0, vbl1);
            mma16816(oacc, pal0, pal1, pal2, pal3, vbh0, vbh1);
        }
        __syncthreads();
    }

    // write O: warp w -> head cols [w*8, w*8+8)
    {
        int col = h * KS_ + w * 8 + 2 * qq;
        size_t r0 = (size_t)b * S_ + q0 + g;
        *(float2*)&Cm[r0 * D_ + col]       = make_float2(oacc[0], oacc[1]);
        *(float2*)&Cm[(r0 + 8) * D_ + col] = make_float2(oacc[2], oacc[3]);
    }
}

// ---------------------------------------------------------------------------
extern "C" void kernel_launch(void* const* d_in, const int* in_sizes, int n_in,
                              void* d_out, int out_size) {
    const float* q    = (const float*)d_in[0];
    const float* v    = (const float*)d_in[1];
    const float* mask = (const float*)d_in[2];
    const float* wq_w = (const float*)d_in[3];
    const float* wq_b = (const float*)d_in[4];
    const float* wk_w = (const float*)d_in[5];
    const float* wk_b = (const float*)d_in[6];
    const float* wv_w = (const float*)d_in[7];
    const float* wv_b = (const float*)d_in[8];
    const float* wo_w = (const float*)d_in[9];
    const float* wo_b = (const float*)d_in[10];

    float* out = (float*)d_out;
    float* heads = out;
    float* align = out + NTOK;

    float* scratch = nullptr;
    cudaGetSymbolAddress((void**)&scratch, g_scratch);
    float* Qm = scratch;
    float* Km = scratch + NTOK;
    float* Vm = scratch + 2 * NTOK;
    float* Cm = scratch + 3 * NTOK;

    float* fb = scratch + 4 * NTOK;
    __nv_bfloat16* AqH = (__nv_bfloat16*)(fb);
    __nv_bfloat16* AqL = (__nv_bfloat16*)(fb + F_ACT);
    __nv_bfloat16* AvH = (__nv_bfloat16*)(fb + 2 * F_ACT);
    __nv_bfloat16* AvL = (__nv_bfloat16*)(fb + 3 * F_ACT);
    float* wb = fb + 4 * F_ACT;
    __nv_bfloat16* WqH = (__nv_bfloat16*)(wb + 0 * F_W);
    __nv_bfloat16* WqL = (__nv_bfloat16*)(wb + 1 * F_W);
    __nv_bfloat16* WkH = (__nv_bfloat16*)(wb + 2 * F_W);
    __nv_bfloat16* WkL = (__nv_bfloat16*)(wb + 3 * F_W);
    __nv_bfloat16* WvH = (__nv_bfloat16*)(wb + 4 * F_W);
    __nv_bfloat16* WvL = (__nv_bfloat16*)(wb + 5 * F_W);
    __nv_bfloat16* WoH = (__nv_bfloat16*)(wb + 6 * F_W);
    __nv_bfloat16* WoL = (__nv_bfloat16*)(wb + 7 * F_W);

    cudaFuncSetAttribute(gemm_mma, cudaFuncAttributeMaxDynamicSharedMemorySize, GSMEM);
    cudaFuncSetAttribute(fused_attn, cudaFuncAttributeMaxDynamicSharedMemorySize, FA_SMEM);

    dim3 gconvW(32, 32);
    dim3 bconvW(32, 8);
    int nAct = (int)NTOK;
    int gA = (nAct / 4 + 255) / 256;

    // conversions
    conv_w<<<gconvW, bconvW>>>(wq_w, WqH, WqL);
    conv_w<<<gconvW, bconvW>>>(wk_w, WkH, WkL);
    conv_w<<<gconvW, bconvW>>>(wv_w, WvH, WvL);
    conv_w<<<gconvW, bconvW>>>(wo_w, WoH, WoL);
    conv_act<<<gA, 256>>>(q, AqH, AqL, nAct);
    conv_act<<<gA, 256>>>(v, AvH, AvL, nAct);

    // projections
    dim3 gproj(D_ / 128, (B_ * S_) / 128);
    gemm_mma<<<gproj, 256, GSMEM>>>(AqH, AqL, WqH, WqL, wq_b, Qm);
    gemm_mma<<<gproj, 256, GSMEM>>>(AvH, AvL, WkH, WkL, wk_b, Km);
    gemm_mma<<<gproj, 256, GSMEM>>>(AvH, AvL, WvH, WvL, wv_b, Vm);

    // split Q/K to bf16 hi/lo (reuse act buffers; stream-serialized)
    conv_act<<<gA, 256>>>(Qm, AqH, AqL, nAct);
    conv_act<<<gA, 256>>>(Km, AvH, AvL, nAct);

    // fused attention: scores + mask + softmax + align-write + context
    dim3 gfa(S_ / RQ, B_ * H_);                 // (128, 32)
    fused_attn<<<gfa, 256, FA_SMEM>>>(AqH, AqL, AvH, AvL, Vm, mask, align, Cm);

    // output projection
    conv_act<<<gA, 256>>>(Cm, AqH, AqL, nAct);
    gemm_mma<<<gproj, 256, GSMEM>>>(AqH, AqL, WoH, WoL, wo_b, heads);
}

// round 7
// speedup vs baseline: 1.5969x; 1.1110x over previous
#include <cuda_runtime.h>
#include <cuda_bf16.h>
#include <cstdint>

#define B_  2
#define S_  2048
#define D_  1024
#define H_  16
#define KS_ 64
#define NEG_BIG (-1.0e9f)

#define NTOK ((size_t)B_ * S_ * D_)

#define F_ACT   (NTOK / 2)            // float slots per bf16 [B,S,D] array
#define F_W     ((size_t)D_ * D_ / 2)
// 10 bf16 act arrays (AqH,AqL,AvH,AvL,QsH,QsL,KsH,KsL,VsH,VsL) + 8 weight arrays
__device__ __align__(16) float g_scratch[10 * F_ACT + 8 * F_W];

typedef uint32_t u32;

// ============================ helpers ======================================
__device__ __forceinline__ u32 smem_u32(const void* p) {
    u32 a;
    asm("{ .reg .u64 t; cvta.to.shared.u64 t, %1; cvt.u32.u64 %0, t; }"
        : "=r"(a) : "l"(p));
    return a;
}
__device__ __forceinline__ void cp_async16(u32 saddr, const void* gaddr) {
    asm volatile("cp.async.cg.shared.global [%0], [%1], 16;"
                 :: "r"(saddr), "l"(gaddr) : "memory");
}
__device__ __forceinline__ void cp_commit() {
    asm volatile("cp.async.commit_group;" ::: "memory");
}
template <int N>
__device__ __forceinline__ void cp_wait() {
    asm volatile("cp.async.wait_group %0;" :: "n"(N) : "memory");
}
__device__ __forceinline__ void mma16816(float* d, u32 a0, u32 a1,
                                         u32 a2, u32 a3, u32 b0, u32 b1) {
    asm volatile(
        "mma.sync.aligned.m16n8k16.row.col.f32.bf16.bf16.f32 "
        "{%0,%1,%2,%3}, {%4,%5,%6,%7}, {%8,%9}, {%0,%1,%2,%3};"
        : "+f"(d[0]), "+f"(d[1]), "+f"(d[2]), "+f"(d[3])
        : "r"(a0), "r"(a1), "r"(a2), "r"(a3), "r"(b0), "r"(b1));
}
__device__ __forceinline__ u32 prmt(u32 a, u32 b, u32 s) {
    u32 d; asm("prmt.b32 %0,%1,%2,%3;" : "=r"(d) : "r"(a), "r"(b), "r"(s));
    return d;
}
__device__ __forceinline__ void ldsm_x2_t(u32& r0, u32& r1, u32 a) {
    asm volatile("ldmatrix.sync.aligned.m8n8.x2.trans.shared.b16 {%0,%1}, [%2];"
                 : "=r"(r0), "=r"(r1) : "r"(a));
}
__device__ __forceinline__ u32 f2bf_bits(float x) {
    u32 u = __float_as_uint(x);
    return (u + 0x7FFFu + ((u >> 16) & 1u)) >> 16;
}
__device__ __forceinline__ float exp_fast(float x) {
    x = fmaxf(x, -87.3f);
    float y = x * 1.44269504089f;
    float n = rintf(y);
    float f = y - n;
    float p = 1.33336498402e-3f;
    p = fmaf(p, f, 9.61793571616e-3f);
    p = fmaf(p, f, 5.55043442248e-2f);
    p = fmaf(p, f, 2.40226506959e-1f);
    p = fmaf(p, f, 6.93147180560e-1f);
    p = fmaf(p, f, 1.0f);
    return __int_as_float(__float_as_int(p) + (((int)n) << 23));
}

// ======================= conversion kernels ================================
__global__ void conv_act(const float* __restrict__ x,
                         __nv_bfloat16* __restrict__ h,
                         __nv_bfloat16* __restrict__ l, int n) {
    int i = blockIdx.x * blockDim.x + threadIdx.x;
    int i4 = i * 4;
    if (i4 >= n) return;
    float4 v = *(const float4*)(x + i4);
    float vs[4] = {v.x, v.y, v.z, v.w};
    __nv_bfloat16 hh[4], ll[4];
    #pragma unroll
    for (int j = 0; j < 4; j++) {
        __nv_bfloat16 hi = __float2bfloat16_rn(vs[j]);
        float r = vs[j] - __bfloat162float(hi);
        hh[j] = hi;
        ll[j] = __float2bfloat16_rn(r);
    }
    __nv_bfloat162* H2 = (__nv_bfloat162*)(h + i4);
    __nv_bfloat162* L2 = (__nv_bfloat162*)(l + i4);
    H2[0] = __nv_bfloat162(hh[0], hh[1]);
    H2[1] = __nv_bfloat162(hh[2], hh[3]);
    L2[0] = __nv_bfloat162(ll[0], ll[1]);
    L2[1] = __nv_bfloat162(ll[2], ll[3]);
}

__global__ void conv_w(const float* __restrict__ W,
                       __nv_bfloat16* __restrict__ Th,
                       __nv_bfloat16* __restrict__ Tl) {
    __shared__ float t[32][33];
    int n0 = blockIdx.x * 32, k0 = blockIdx.y * 32;
    int tx = threadIdx.x, ty = threadIdx.y;
    for (int r = ty; r < 32; r += 8)
        t[r][tx] = W[(size_t)(k0 + r) * D_ + n0 + tx];
    __syncthreads();
    for (int r = ty; r < 32; r += 8) {
        float x = t[tx][r];
        __nv_bfloat16 hi = __float2bfloat16_rn(x);
        float res = x - __bfloat162float(hi);
        size_t o = (size_t)(n0 + r) * D_ + k0 + tx;
        Th[o] = hi;
        Tl[o] = __float2bfloat16_rn(res);
    }
}

// ======================= HMMA GEMM core ====================================
#define GROW   80
#define GTILE  (128 * GROW)
#define GSTAGE (4 * GTILE)
#define GSMEM  (2 * GSTAGE)

// mainloop shared by both epilogues
#define GEMM_BODY(ACC)                                                          \
    const u32 sb = smem_u32(smem);                                              \
    const int tid  = threadIdx.x;                                               \
    const int lane = tid & 31;                                                  \
    const int wid  = tid >> 5;                                                  \
    const int wm   = wid >> 2;                                                  \
    const int wn   = wid & 3;                                                   \
    const int g    = lane >> 2;                                                 \
    const int q    = lane & 3;                                                  \
    const int n0 = blockIdx.x * 128;                                            \
    const int m0 = blockIdx.y * 128;                                            \
    const int cid0 = tid * 2;                                                   \
    const int row0 = cid0 >> 2;                                                 \
    const int cc0  = (cid0 & 3) * 8;                                            \
    const int row1 = (cid0 + 1) >> 2;                                           \
    const int cc1  = ((cid0 + 1) & 3) * 8;                                      \
    const int NK = D_ / 32;                                                     \
    {                                                                           \
        u32 s = sb;                                                             \
        cp_async16(s + 0 * GTILE + row0 * GROW + (cc0 & 31) * 2, Ah + (size_t)(m0 + row0) * D_ + cc0); \
        cp_async16(s + 0 * GTILE + row1 * GROW + (cc1 & 31) * 2, Ah + (size_t)(m0 + row1) * D_ + cc1); \
        cp_async16(s + 1 * GTILE + row0 * GROW + (cc0 & 31) * 2, Al + (size_t)(m0 + row0) * D_ + cc0); \
        cp_async16(s + 1 * GTILE + row1 * GROW + (cc1 & 31) * 2, Al + (size_t)(m0 + row1) * D_ + cc1); \
        cp_async16(s + 2 * GTILE + row0 * GROW + (cc0 & 31) * 2, Bh + (size_t)(n0 + row0) * D_ + cc0); \
        cp_async16(s + 2 * GTILE + row1 * GROW + (cc1 & 31) * 2, Bh + (size_t)(n0 + row1) * D_ + cc1); \
        cp_async16(s + 3 * GTILE + row0 * GROW + (cc0 & 31) * 2, Bl + (size_t)(n0 + row0) * D_ + cc0); \
        cp_async16(s + 3 * GTILE + row1 * GROW + (cc1 & 31) * 2, Bl + (size_t)(n0 + row1) * D_ + cc1); \
        cp_commit();                                                            \
    }                                                                           \
    for (int ks = 0; ks < NK; ks++) {                                           \
        if (ks + 1 < NK) {                                                      \
            int k0 = (ks + 1) * 32;                                             \
            u32 s = sb + ((ks + 1) & 1) * GSTAGE;                               \
            cp_async16(s + 0 * GTILE + row0 * GROW + (cc0 & 31) * 2, Ah + (size_t)(m0 + row0) * D_ + k0 + cc0); \
            cp_async16(s + 0 * GTILE + row1 * GROW + (cc1 & 31) * 2, Ah + (size_t)(m0 + row1) * D_ + k0 + cc1); \
            cp_async16(s + 1 * GTILE + row0 * GROW + (cc0 & 31) * 2, Al + (size_t)(m0 + row0) * D_ + k0 + cc0); \
            cp_async16(s + 1 * GTILE + row1 * GROW + (cc1 & 31) * 2, Al + (size_t)(m0 + row1) * D_ + k0 + cc1); \
            cp_async16(s + 2 * GTILE + row0 * GROW + (cc0 & 31) * 2, Bh + (size_t)(n0 + row0) * D_ + k0 + cc0); \
            cp_async16(s + 2 * GTILE + row1 * GROW + (cc1 & 31) * 2, Bh + (size_t)(n0 + row1) * D_ + k0 + cc1); \
            cp_async16(s + 3 * GTILE + row0 * GROW + (cc0 & 31) * 2, Bl + (size_t)(n0 + row0) * D_ + k0 + cc0); \
            cp_async16(s + 3 * GTILE + row1 * GROW + (cc1 & 31) * 2, Bl + (size_t)(n0 + row1) * D_ + k0 + cc1); \
            cp_commit();                                                        \
            cp_wait<1>();                                                       \
        } else {                                                                \
            cp_wait<0>();                                                       \
        }                                                                       \
        __syncthreads();                                                        \
        const char* st  = smem + (ks & 1) * GSTAGE;                             \
        const char* sAh = st;                                                   \
        const char* sAl = st + GTILE;                                           \
        const char* sBh = st + 2 * GTILE;                                       \
        const char* sBl = st + 3 * GTILE;                                       \
        _Pragma("unroll")                                                       \
        for (int kk = 0; kk < 32; kk += 16) {                                   \
            u32 bh[4][2], bl[4][2];                                             \
            _Pragma("unroll")                                                   \
            for (int j = 0; j < 4; j++) {                                       \
                int n = wn * 32 + j * 8 + g;                                    \
                int o0 = n * GROW + (kk + 2 * q) * 2;                           \
                int o1 = n * GROW + (kk + 2 * q + 8) * 2;                       \
                bh[j][0] = *(const u32*)(sBh + o0);                             \
                bh[j][1] = *(const u32*)(sBh + o1);                             \
                bl[j][0] = *(const u32*)(sBl + o0);                             \
                bl[j][1] = *(const u32*)(sBl + o1);                             \
            }                                                                   \
            _Pragma("unroll")                                                   \
            for (int i = 0; i < 4; i++) {                                       \
                int m = wm * 64 + i * 16;                                       \
                int r0 = (m + g) * GROW;                                        \
                int r1 = (m + g + 8) * GROW;                                    \
                int c0 = (kk + 2 * q) * 2;                                      \
                int c1 = (kk + 2 * q + 8) * 2;                                  \
                u32 ah0 = *(const u32*)(sAh + r0 + c0);                         \
                u32 ah1 = *(const u32*)(sAh + r1 + c0);                         \
                u32 ah2 = *(const u32*)(sAh + r0 + c1);                         \
                u32 ah3 = *(const u32*)(sAh + r1 + c1);                         \
                u32 al0 = *(const u32*)(sAl + r0 + c0);                         \
                u32 al1 = *(const u32*)(sAl + r1 + c0);                         \
                u32 al2 = *(const u32*)(sAl + r0 + c1);                         \
                u32 al3 = *(const u32*)(sAl + r1 + c1);                         \
                _Pragma("unroll")                                               \
                for (int j = 0; j < 4; j++) {                                   \
                    mma16816(ACC[i][j], ah0, ah1, ah2, ah3, bh[j][0], bh[j][1]);\
                    mma16816(ACC[i][j], ah0, ah1, ah2, ah3, bl[j][0], bl[j][1]);\
                    mma16816(ACC[i][j], al0, al1, al2, al3, bh[j][0], bh[j][1]);\
                }                                                               \
            }                                                                   \
        }                                                                       \
        __syncthreads();                                                        \
    }

// fp32 output + bias (final projection)
__global__ void __launch_bounds__(256) gemm_mma(
    const __nv_bfloat16* __restrict__ Ah, const __nv_bfloat16* __restrict__ Al,
    const __nv_bfloat16* __restrict__ Bh, const __nv_bfloat16* __restrict__ Bl,
    const float* __restrict__ bias, float* __restrict__ C) {
    extern __shared__ char smem[];
    float acc[4][4][4] = {};
    GEMM_BODY(acc)
    #pragma unroll
    for (int i = 0; i < 4; i++) {
        int row = m0 + wm * 64 + i * 16;
        #pragma unroll
        for (int j = 0; j < 4; j++) {
            int col = n0 + wn * 32 + j * 8 + 2 * q;
            float b0 = __ldg(bias + col);
            float b1 = __ldg(bias + col + 1);
            float2 v0 = make_float2(acc[i][j][0] + b0, acc[i][j][1] + b1);
            float2 v1 = make_float2(acc[i][j][2] + b0, acc[i][j][3] + b1);
            *(float2*)&C[(size_t)(row + g) * D_ + col]     = v0;
            *(float2*)&C[(size_t)(row + g + 8) * D_ + col] = v1;
        }
    }
}

// bf16 hi/lo split output + bias (Q/K/V projections)
__global__ void __launch_bounds__(256) gemm_split(
    const __nv_bfloat16* __restrict__ Ah, const __nv_bfloat16* __restrict__ Al,
    const __nv_bfloat16* __restrict__ Bh, const __nv_bfloat16* __restrict__ Bl,
    const float* __restrict__ bias,
    __nv_bfloat16* __restrict__ Ch, __nv_bfloat16* __restrict__ Cl) {
    extern __shared__ char smem[];
    float acc[4][4][4] = {};
    GEMM_BODY(acc)
    #pragma unroll
    for (int i = 0; i < 4; i++) {
        int row = m0 + wm * 64 + i * 16;
        #pragma unroll
        for (int j = 0; j < 4; j++) {
            int col = n0 + wn * 32 + j * 8 + 2 * q;
            float b0 = __ldg(bias + col);
            float b1 = __ldg(bias + col + 1);
            float vs[4] = {acc[i][j][0] + b0, acc[i][j][1] + b1,
                           acc[i][j][2] + b0, acc[i][j][3] + b1};
            u32 hb[4], lb[4];
            #pragma unroll
            for (int t = 0; t < 4; t++) {
                hb[t] = f2bf_bits(vs[t]);
                lb[t] = f2bf_bits(vs[t] - __uint_as_float(hb[t] << 16));
            }
            size_t o0 = (size_t)(row + g) * D_ + col;
            size_t o1 = (size_t)(row + g + 8) * D_ + col;
            *(u32*)&Ch[o0] = hb[0] | (hb[1] << 16);
            *(u32*)&Cl[o0] = lb[0] | (lb[1] << 16);
            *(u32*)&Ch[o1] = hb[2] | (hb[3] << 16);
            *(u32*)&Cl[o1] = lb[2] | (lb[3] << 16);
        }
    }
}

// ======================= fused attention (512 threads) =====================
#define RQ 16
#define CK 128
#define SROW 2056
#define SC_BYTES (RQ * SROW * 4)           // 131584
#define KROW 144
#define KTILE (CK * KROW)                  // 18432
#define KSTG  (2 * KTILE)                  // 36864
#define KA_OFF SC_BYTES
#define Q_OFF (KA_OFF + 2 * KSTG)          // 205312
#define QTILE (RQ * KROW)                  // 2304
#define FA_SMEM (Q_OFF + 2 * QTILE)        // 209920
#define FT 512

__device__ __forceinline__ void stage_pair_chunk(
    u32 sb, const __nv_bfloat16* Xh, const __nv_bfloat16* Xl,
    int b, int h, int c, int buf, int tid) {
    #pragma unroll
    for (int i = tid; i < 2048; i += FT) {
        int which = i >> 10, j = i & 1023, row = j >> 3, sub = j & 7;
        const __nv_bfloat16* src = (which ? Xl : Xh) +
            ((size_t)b * S_ + (size_t)c * CK + row) * D_ + h * KS_ + sub * 8;
        cp_async16(sb + KA_OFF + buf * KSTG + which * KTILE + row * KROW + sub * 16, src);
    }
}

__global__ void __launch_bounds__(FT) fused_attn(
    const __nv_bfloat16* __restrict__ Qh, const __nv_bfloat16* __restrict__ Ql,
    const __nv_bfloat16* __restrict__ Kh, const __nv_bfloat16* __restrict__ Kl,
    const __nv_bfloat16* __restrict__ Vh, const __nv_bfloat16* __restrict__ Vl,
    const float* __restrict__ mask, float* __restrict__ align,
    __nv_bfloat16* __restrict__ CtxH, __nv_bfloat16* __restrict__ CtxL) {
    extern __shared__ char smem[];
    const u32 sb = smem_u32(smem);
    float* sc = (float*)smem;
    u32* scu = (u32*)smem;

    const int tid = threadIdx.x, lane = tid & 31, w = tid >> 5;  // w: 0..15
    const int g = lane >> 2, qq = lane & 3;
    const int bh = blockIdx.y, b = bh >> 4, h = bh & 15;
    const int q0 = blockIdx.x * RQ;

    // stage Q (256 cp.async)
    if (tid < 256) {
        int which = tid >> 7, j = tid & 127, row = j >> 3, sub = j & 7;
        const __nv_bfloat16* src = (which ? Ql : Qh) +
            ((size_t)b * S_ + q0 + row) * D_ + h * KS_ + sub * 8;
        cp_async16(sb + Q_OFF + which * QTILE + row * KROW + sub * 16, src);
    }
    stage_pair_chunk(sb, Kh, Kl, b, h, 0, 0, tid);
    cp_commit();

    u32 ah[4][4], al[4][4];
    const float* mrow = mask + (size_t)b * S_ * S_;

    // =================== phase 1: scores ===================
    for (int c = 0; c < 16; c++) {
        if (c + 1 < 16) {
            stage_pair_chunk(sb, Kh, Kl, b, h, c + 1, (c + 1) & 1, tid);
            cp_commit();
            cp_wait<1>();
        } else {
            cp_wait<0>();
        }
        __syncthreads();

        if (c == 0) {
            const char* sQh = smem + Q_OFF;
            const char* sQl = smem + Q_OFF + QTILE;
            #pragma unroll
            for (int ks = 0; ks < 4; ks++) {
                int c0 = (ks * 16 + 2 * qq) * 2, c1 = c0 + 16;
                ah[ks][0] = *(const u32*)(sQh + g * KROW + c0);
                ah[ks][1] = *(const u32*)(sQh + (g + 8) * KROW + c0);
                ah[ks][2] = *(const u32*)(sQh + g * KROW + c1);
                ah[ks][3] = *(const u32*)(sQh + (g + 8) * KROW + c1);
                al[ks][0] = *(const u32*)(sQl + g * KROW + c0);
                al[ks][1] = *(const u32*)(sQl + (g + 8) * KROW + c0);
                al[ks][2] = *(const u32*)(sQl + g * KROW + c1);
                al[ks][3] = *(const u32*)(sQl + (g + 8) * KROW + c1);
            }
        }

        const char* sKh = smem + KA_OFF + (c & 1) * KSTG;
        const char* sKl = sKh + KTILE;

        {
            float acc[4] = {0.f, 0.f, 0.f, 0.f};
            int nbase = w * 8;                 // 16 warps x 8 cols = 128
            #pragma unroll
            for (int ks = 0; ks < 4; ks++) {
                int ko = (ks * 16 + 2 * qq) * 2;
                u32 bh0 = *(const u32*)(sKh + (nbase + g) * KROW + ko);
                u32 bh1 = *(const u32*)(sKh + (nbase + g) * KROW + ko + 16);
                u32 bl0 = *(const u32*)(sKl + (nbase + g) * KROW + ko);
                u32 bl1 = *(const u32*)(sKl + (nbase + g) * KROW + ko + 16);
                mma16816(acc, ah[ks][0], ah[ks][1], ah[ks][2], ah[ks][3], bh0, bh1);
                mma16816(acc, ah[ks][0], ah[ks][1], ah[ks][2], ah[ks][3], bl0, bl1);
                mma16816(acc, al[ks][0], al[ks][1], al[ks][2], al[ks][3], bh0, bh1);
            }
            int col = c * 128 + nbase + 2 * qq;
            int r0 = q0 + g, r1 = q0 + g + 8;
            float2 m0 = *(const float2*)&mrow[(size_t)r0 * S_ + col];
            float2 m1 = *(const float2*)&mrow[(size_t)r1 * S_ + col];
            float s0 = acc[0] * 0.125f * m0.x; if (s0 == 0.0f) s0 = NEG_BIG;
            float s1 = acc[1] * 0.125f * m0.y; if (s1 == 0.0f) s1 = NEG_BIG;
            float s2 = acc[2] * 0.125f * m1.x; if (s2 == 0.0f) s2 = NEG_BIG;
            float s3 = acc[3] * 0.125f * m1.y; if (s3 == 0.0f) s3 = NEG_BIG;
            *(float2*)&sc[g * SROW + col]       = make_float2(s0, s1);
            *(float2*)&sc[(g + 8) * SROW + col] = make_float2(s2, s3);
        }
        __syncthreads();
    }

    // =================== phase 2: softmax (1 row / warp) ===================
    {
        int r = w;
        float* row = sc + r * SROW;
        float mx = -3.402823466e38f;
        for (int i = lane; i < S_; i += 32) mx = fmaxf(mx, row[i]);
        #pragma unroll
        for (int o = 16; o > 0; o >>= 1) mx = fmaxf(mx, __shfl_xor_sync(0xffffffffu, mx, o));
        float sm = 0.f;
        for (int i = lane; i < S_; i += 32) {
            float e = exp_fast(row[i] - mx);
            row[i] = e;
            sm += e;
        }
        #pragma unroll
        for (int o = 16; o > 0; o >>= 1) sm += __shfl_xor_sync(0xffffffffu, sm, o);
        float inv = 1.0f / sm;
        float* arow = align + ((size_t)bh * S_ + q0 + r) * S_;
        u32* prow = (u32*)row;
        for (int i = lane; i < S_; i += 32) {
            float p = row[i] * inv;
            arow[i] = p;
            u32 hb = f2bf_bits(p);
            float res = p - __uint_as_float(hb << 16);
            prow[i] = hb | (f2bf_bits(res) << 16);
        }
    }
    __syncthreads();

    // =================== phase 3: O = P.V (k-split across warp halves) =====
    const int kr = w >> 3, wc = w & 7;
    float oacc[4] = {0.f, 0.f, 0.f, 0.f};
    for (int it = 0; it < 8; it++) {
        // stage chunk it into buf0 and chunk it+8 into buf1 (4096 cp.async)
        #pragma unroll
        for (int i = tid; i < 4096; i += FT) {
            int half = i >> 11, j = i & 2047;
            int which = j >> 10, jj = j & 1023, row = jj >> 3, sub = jj & 7;
            int cc = half * 8 + it;
            const __nv_bfloat16* src = (which ? Vl : Vh) +
                ((size_t)b * S_ + (size_t)cc * CK + row) * D_ + h * KS_ + sub * 8;
            cp_async16(sb + KA_OFF + half * KSTG + which * KTILE + row * KROW + sub * 16, src);
        }
        cp_commit();
        cp_wait<0>();
        __syncthreads();

        int chunk = kr * 8 + it;
        u32 vbase = sb + KA_OFF + kr * KSTG;
        #pragma unroll
        for (int ks = 0; ks < 8; ks++) {
            int k0 = chunk * 128 + ks * 16 + 2 * qq;
            uint2 w0 = *(const uint2*)&scu[g * SROW + k0];
            uint2 w1 = *(const uint2*)&scu[g * SROW + k0 + 8];
            uint2 w2 = *(const uint2*)&scu[(g + 8) * SROW + k0];
            uint2 w3 = *(const uint2*)&scu[(g + 8) * SROW + k0 + 8];
            u32 pah0 = prmt(w0.x, w0.y, 0x5410), pal0 = prmt(w0.x, w0.y, 0x7632);
            u32 pah1 = prmt(w2.x, w2.y, 0x5410), pal1 = prmt(w2.x, w2.y, 0x7632);
            u32 pah2 = prmt(w1.x, w1.y, 0x5410), pal2 = prmt(w1.x, w1.y, 0x7632);
            u32 pah3 = prmt(w3.x, w3.y, 0x5410), pal3 = prmt(w3.x, w3.y, 0x7632);

            u32 addr = vbase + (ks * 16 + (lane & 15)) * KROW + wc * 16;
            u32 vbh0, vbh1, vbl0, vbl1;
            ldsm_x2_t(vbh0, vbh1, addr);
            ldsm_x2_t(vbl0, vbl1, addr + KTILE);

            mma16816(oacc, pah0, pah1, pah2, pah3, vbh0, vbh1);
            mma16816(oacc, pah0, pah1, pah2, pah3, vbl0, vbl1);
            mma16816(oacc, pal0, pal1, pal2, pal3, vbh0, vbh1);
        }
        __syncthreads();
    }

    // reduce halves: kr=1 warps store partials, kr=0 adds + writes bf16 split
    float* red = (float*)(smem + Q_OFF);
    if (kr == 1) {
        float4* dst = (float4*)red;
        dst[(w - 8) * 32 + lane] = make_float4(oacc[0], oacc[1], oacc[2], oacc[3]);
    }
    __syncthreads();
    if (kr == 0) {
        float4 pp = ((float4*)red)[w * 32 + lane];
        oacc[0] += pp.x; oacc[1] += pp.y; oacc[2] += pp.z; oacc[3] += pp.w;
        int col = h * KS_ + wc * 8 + 2 * qq;
        size_t o0 = ((size_t)b * S_ + q0 + g) * D_ + col;
        size_t o1 = o0 + 8 * D_;
        u32 hb0 = f2bf_bits(oacc[0]), hb1 = f2bf_bits(oacc[1]);
        u32 hb2 = f2bf_bits(oacc[2]), hb3 = f2bf_bits(oacc[3]);
        u32 lb0 = f2bf_bits(oacc[0] - __uint_as_float(hb0 << 16));
        u32 lb1 = f2bf_bits(oacc[1] - __uint_as_float(hb1 << 16));
        u32 lb2 = f2bf_bits(oacc[2] - __uint_as_float(hb2 << 16));
        u32 lb3 = f2bf_bits(oacc[3] - __uint_as_float(hb3 << 16));
        *(u32*)&CtxH[o0] = hb0 | (hb1 << 16);
        *(u32*)&CtxL[o0] = lb0 | (lb1 << 16);
        *(u32*)&CtxH[o1] = hb2 | (hb3 << 16);
        *(u32*)&CtxL[o1] = lb2 | (lb3 << 16);
    }
}

// ---------------------------------------------------------------------------
extern "C" void kernel_launch(void* const* d_in, const int* in_sizes, int n_in,
                              void* d_out, int out_size) {
    const float* q    = (const float*)d_in[0];
    const float* v    = (const float*)d_in[1];
    const float* mask = (const float*)d_in[2];
    const float* wq_w = (const float*)d_in[3];
    const float* wq_b = (const float*)d_in[4];
    const float* wk_w = (const float*)d_in[5];
    const float* wk_b = (const float*)d_in[6];
    const float* wv_w = (const float*)d_in[7];
    const float* wv_b = (const float*)d_in[8];
    const float* wo_w = (const float*)d_in[9];
    const float* wo_b = (const float*)d_in[10];

    float* out = (float*)d_out;
    float* heads = out;
    float* align = out + NTOK;

    float* scratch = nullptr;
    cudaGetSymbolAddress((void**)&scratch, g_scratch);

    __nv_bfloat16* AqH = (__nv_bfloat16*)(scratch + 0 * F_ACT);
    __nv_bfloat16* AqL = (__nv_bfloat16*)(scratch + 1 * F_ACT);
    __nv_bfloat16* AvH = (__nv_bfloat16*)(scratch + 2 * F_ACT);
    __nv_bfloat16* AvL = (__nv_bfloat16*)(scratch + 3 * F_ACT);
    __nv_bfloat16* QsH = (__nv_bfloat16*)(scratch + 4 * F_ACT);
    __nv_bfloat16* QsL = (__nv_bfloat16*)(scratch + 5 * F_ACT);
    __nv_bfloat16* KsH = (__nv_bfloat16*)(scratch + 6 * F_ACT);
    __nv_bfloat16* KsL = (__nv_bfloat16*)(scratch + 7 * F_ACT);
    __nv_bfloat16* VsH = (__nv_bfloat16*)(scratch + 8 * F_ACT);
    __nv_bfloat16* VsL = (__nv_bfloat16*)(scratch + 9 * F_ACT);
    float* wb = scratch + 10 * F_ACT;
    __nv_bfloat16* WqH = (__nv_bfloat16*)(wb + 0 * F_W);
    __nv_bfloat16* WqL = (__nv_bfloat16*)(wb + 1 * F_W);
    __nv_bfloat16* WkH = (__nv_bfloat16*)(wb + 2 * F_W);
    __nv_bfloat16* WkL = (__nv_bfloat16*)(wb + 3 * F_W);
    __nv_bfloat16* WvH = (__nv_bfloat16*)(wb + 4 * F_W);
    __nv_bfloat16* WvL = (__nv_bfloat16*)(wb + 5 * F_W);
    __nv_bfloat16* WoH = (__nv_bfloat16*)(wb + 6 * F_W);
    __nv_bfloat16* WoL = (__nv_bfloat16*)(wb + 7 * F_W);

    cudaFuncSetAttribute(gemm_mma, cudaFuncAttributeMaxDynamicSharedMemorySize, GSMEM);
    cudaFuncSetAttribute(gemm_split, cudaFuncAttributeMaxDynamicSharedMemorySize, GSMEM);
    cudaFuncSetAttribute(fused_attn, cudaFuncAttributeMaxDynamicSharedMemorySize, FA_SMEM);

    dim3 gconvW(32, 32);
    dim3 bconvW(32, 8);
    int nAct = (int)NTOK;
    int gA = (nAct / 4 + 255) / 256;

    conv_w<<<gconvW, bconvW>>>(wq_w, WqH, WqL);
    conv_w<<<gconvW, bconvW>>>(wk_w, WkH, WkL);
    conv_w<<<gconvW, bconvW>>>(wv_w, WvH, WvL);
    conv_w<<<gconvW, bconvW>>>(wo_w, WoH, WoL);
    conv_act<<<gA, 256>>>(q, AqH, AqL, nAct);
    conv_act<<<gA, 256>>>(v, AvH, AvL, nAct);

    dim3 gproj(D_ / 128, (B_ * S_) / 128);
    gemm_split<<<gproj, 256, GSMEM>>>(AqH, AqL, WqH, WqL, wq_b, QsH, QsL);
    gemm_split<<<gproj, 256, GSMEM>>>(AvH, AvL, WkH, WkL, wk_b, KsH, KsL);
    gemm_split<<<gproj, 256, GSMEM>>>(AvH, AvL, WvH, WvL, wv_b, VsH, VsL);

    dim3 gfa(S_ / RQ, B_ * H_);
    // Ctx written into AqH/AqL (input q-splits consumed by Q projection)
    fused_attn<<<gfa, FT, FA_SMEM>>>(QsH, QsL, KsH, KsL, VsH, VsL,
                                     mask, align, AqH, AqL);

    gemm_mma<<<gproj, 256, GSMEM>>>(AqH, AqL, WoH, WoL, wo_b, heads);
}

// round 9
// speedup vs baseline: 1.6455x; 1.0304x over previous
#include <cuda_runtime.h>
#include <cuda_bf16.h>
#include <cstdint>

#define B_  2
#define S_  2048
#define D_  1024
#define H_  16
#define KS_ 64
#define NEG_BIG (-1.0e9f)

#define NTOK ((size_t)B_ * S_ * D_)

#define F_ACT   (NTOK / 2)            // float slots per bf16 [B,S,D] array
#define F_W     ((size_t)D_ * D_ / 2)
__device__ __align__(16) float g_scratch[10 * F_ACT + 8 * F_W];

typedef uint32_t u32;

// ============================ helpers ======================================
__device__ __forceinline__ u32 smem_u32(const void* p) {
    u32 a;
    asm("{ .reg .u64 t; cvta.to.shared.u64 t, %1; cvt.u32.u64 %0, t; }"
        : "=r"(a) : "l"(p));
    return a;
}
__device__ __forceinline__ void cp_async16(u32 saddr, const void* gaddr) {
    asm volatile("cp.async.cg.shared.global [%0], [%1], 16;"
                 :: "r"(saddr), "l"(gaddr) : "memory");
}
__device__ __forceinline__ void cp_commit() {
    asm volatile("cp.async.commit_group;" ::: "memory");
}
template <int N>
__device__ __forceinline__ void cp_wait() {
    asm volatile("cp.async.wait_group %0;" :: "n"(N) : "memory");
}
__device__ __forceinline__ void mma16816(float* d, u32 a0, u32 a1,
                                         u32 a2, u32 a3, u32 b0, u32 b1) {
    asm volatile(
        "mma.sync.aligned.m16n8k16.row.col.f32.bf16.bf16.f32 "
        "{%0,%1,%2,%3}, {%4,%5,%6,%7}, {%8,%9}, {%0,%1,%2,%3};"
        : "+f"(d[0]), "+f"(d[1]), "+f"(d[2]), "+f"(d[3])
        : "r"(a0), "r"(a1), "r"(a2), "r"(a3), "r"(b0), "r"(b1));
}
__device__ __forceinline__ u32 prmt(u32 a, u32 b, u32 s) {
    u32 d; asm("prmt.b32 %0,%1,%2,%3;" : "=r"(d) : "r"(a), "r"(b), "r"(s));
    return d;
}
__device__ __forceinline__ void ldsm_x2_t(u32& r0, u32& r1, u32 a) {
    asm volatile("ldmatrix.sync.aligned.m8n8.x2.trans.shared.b16 {%0,%1}, [%2];"
                 : "=r"(r0), "=r"(r1) : "r"(a));
}
__device__ __forceinline__ u32 f2bf_bits(float x) {
    u32 u = __float_as_uint(x);
    return (u + 0x7FFFu + ((u >> 16) & 1u)) >> 16;
}
__device__ __forceinline__ float exp_fast(float x) {
    x = fmaxf(x, -87.3f);
    float y = x * 1.44269504089f;
    float n = rintf(y);
    float f = y - n;
    float p = 1.33336498402e-3f;
    p = fmaf(p, f, 9.61793571616e-3f);
    p = fmaf(p, f, 5.55043442248e-2f);
    p = fmaf(p, f, 2.40226506959e-1f);
    p = fmaf(p, f, 6.93147180560e-1f);
    p = fmaf(p, f, 1.0f);
    return __int_as_float(__float_as_int(p) + (((int)n) << 23));
}

// ======================= conversion kernels ================================
__global__ void conv_act(const float* __restrict__ x,
                         __nv_bfloat16* __restrict__ h,
                         __nv_bfloat16* __restrict__ l, int n) {
    int i = blockIdx.x * blockDim.x + threadIdx.x;
    int i4 = i * 4;
    if (i4 >= n) return;
    float4 v = *(const float4*)(x + i4);
    float vs[4] = {v.x, v.y, v.z, v.w};
    __nv_bfloat16 hh[4], ll[4];
    #pragma unroll
    for (int j = 0; j < 4; j++) {
        __nv_bfloat16 hi = __float2bfloat16_rn(vs[j]);
        float r = vs[j] - __bfloat162float(hi);
        hh[j] = hi;
        ll[j] = __float2bfloat16_rn(r);
    }
    __nv_bfloat162* H2 = (__nv_bfloat162*)(h + i4);
    __nv_bfloat162* L2 = (__nv_bfloat162*)(l + i4);
    H2[0] = __nv_bfloat162(hh[0], hh[1]);
    H2[1] = __nv_bfloat162(hh[2], hh[3]);
    L2[0] = __nv_bfloat162(ll[0], ll[1]);
    L2[1] = __nv_bfloat162(ll[2], ll[3]);
}

// all 4 weights in one launch: blockIdx.z selects weight
__global__ void conv_w4(const float* __restrict__ W0, const float* __restrict__ W1,
                        const float* __restrict__ W2, const float* __restrict__ W3,
                        __nv_bfloat16* __restrict__ T0h, __nv_bfloat16* __restrict__ T0l,
                        __nv_bfloat16* __restrict__ T1h, __nv_bfloat16* __restrict__ T1l,
                        __nv_bfloat16* __restrict__ T2h, __nv_bfloat16* __restrict__ T2l,
                        __nv_bfloat16* __restrict__ T3h, __nv_bfloat16* __restrict__ T3l) {
    __shared__ float t[32][33];
    const float* W;
    __nv_bfloat16 *Th, *Tl;
    switch (blockIdx.z) {
        case 0: W = W0; Th = T0h; Tl = T0l; break;
        case 1: W = W1; Th = T1h; Tl = T1l; break;
        case 2: W = W2; Th = T2h; Tl = T2l; break;
        default: W = W3; Th = T3h; Tl = T3l; break;
    }
    int n0 = blockIdx.x * 32, k0 = blockIdx.y * 32;
    int tx = threadIdx.x, ty = threadIdx.y;
    for (int r = ty; r < 32; r += 8)
        t[r][tx] = W[(size_t)(k0 + r) * D_ + n0 + tx];
    __syncthreads();
    for (int r = ty; r < 32; r += 8) {
        float x = t[tx][r];
        __nv_bfloat16 hi = __float2bfloat16_rn(x);
        float res = x - __bfloat162float(hi);
        size_t o = (size_t)(n0 + r) * D_ + k0 + tx;
        Th[o] = hi;
        Tl[o] = __float2bfloat16_rn(res);
    }
}

// ======================= HMMA GEMM core ====================================
#define GROW   80
#define GTILE  (128 * GROW)
#define GSTAGE (4 * GTILE)
#define GSMEM  (2 * GSTAGE)

#define GEMM_BODY(ACC)                                                          \
    const u32 sb = smem_u32(smem);                                              \
    const int tid  = threadIdx.x;                                               \
    const int lane = tid & 31;                                                  \
    const int wid  = tid >> 5;                                                  \
    const int wm   = wid >> 2;                                                  \
    const int wn   = wid & 3;                                                   \
    const int g    = lane >> 2;                                                 \
    const int q    = lane & 3;                                                  \
    const int n0 = blockIdx.x * 128;                                            \
    const int m0 = blockIdx.y * 128;                                            \
    const int cid0 = tid * 2;                                                   \
    const int row0 = cid0 >> 2;                                                 \
    const int cc0  = (cid0 & 3) * 8;                                            \
    const int row1 = (cid0 + 1) >> 2;                                           \
    const int cc1  = ((cid0 + 1) & 3) * 8;                                      \
    const int NK = D_ / 32;                                                     \
    {                                                                           \
        u32 s = sb;                                                             \
        cp_async16(s + 0 * GTILE + row0 * GROW + (cc0 & 31) * 2, Ah + (size_t)(m0 + row0) * D_ + cc0); \
        cp_async16(s + 0 * GTILE + row1 * GROW + (cc1 & 31) * 2, Ah + (size_t)(m0 + row1) * D_ + cc1); \
        cp_async16(s + 1 * GTILE + row0 * GROW + (cc0 & 31) * 2, Al + (size_t)(m0 + row0) * D_ + cc0); \
        cp_async16(s + 1 * GTILE + row1 * GROW + (cc1 & 31) * 2, Al + (size_t)(m0 + row1) * D_ + cc1); \
        cp_async16(s + 2 * GTILE + row0 * GROW + (cc0 & 31) * 2, Bh + (size_t)(n0 + row0) * D_ + cc0); \
        cp_async16(s + 2 * GTILE + row1 * GROW + (cc1 & 31) * 2, Bh + (size_t)(n0 + row1) * D_ + cc1); \
        cp_async16(s + 3 * GTILE + row0 * GROW + (cc0 & 31) * 2, Bl + (size_t)(n0 + row0) * D_ + cc0); \
        cp_async16(s + 3 * GTILE + row1 * GROW + (cc1 & 31) * 2, Bl + (size_t)(n0 + row1) * D_ + cc1); \
        cp_commit();                                                            \
    }                                                                           \
    for (int ks = 0; ks < NK; ks++) {                                           \
        if (ks + 1 < NK) {                                                      \
            int k0 = (ks + 1) * 32;                                             \
            u32 s = sb + ((ks + 1) & 1) * GSTAGE;                               \
            cp_async16(s + 0 * GTILE + row0 * GROW + (cc0 & 31) * 2, Ah + (size_t)(m0 + row0) * D_ + k0 + cc0); \
            cp_async16(s + 0 * GTILE + row1 * GROW + (cc1 & 31) * 2, Ah + (size_t)(m0 + row1) * D_ + k0 + cc1); \
            cp_async16(s + 1 * GTILE + row0 * GROW + (cc0 & 31) * 2, Al + (size_t)(m0 + row0) * D_ + k0 + cc0); \
            cp_async16(s + 1 * GTILE + row1 * GROW + (cc1 & 31) * 2, Al + (size_t)(m0 + row1) * D_ + k0 + cc1); \
            cp_async16(s + 2 * GTILE + row0 * GROW + (cc0 & 31) * 2, Bh + (size_t)(n0 + row0) * D_ + k0 + cc0); \
            cp_async16(s + 2 * GTILE + row1 * GROW + (cc1 & 31) * 2, Bh + (size_t)(n0 + row1) * D_ + k0 + cc1); \
            cp_async16(s + 3 * GTILE + row0 * GROW + (cc0 & 31) * 2, Bl + (size_t)(n0 + row0) * D_ + k0 + cc0); \
            cp_async16(s + 3 * GTILE + row1 * GROW + (cc1 & 31) * 2, Bl + (size_t)(n0 + row1) * D_ + k0 + cc1); \
            cp_commit();                                                        \
            cp_wait<1>();                                                       \
        } else {                                                                \
            cp_wait<0>();                                                       \
        }                                                                       \
        __syncthreads();                                                        \
        const char* st  = smem + (ks & 1) * GSTAGE;                             \
        const char* sAh = st;                                                   \
        const char* sAl = st + GTILE;                                           \
        const char* sBh = st + 2 * GTILE;                                       \
        const char* sBl = st + 3 * GTILE;                                       \
        _Pragma("unroll")                                                       \
        for (int kk = 0; kk < 32; kk += 16) {                                   \
            u32 bh[4][2], bl[4][2];                                             \
            _Pragma("unroll")                                                   \
            for (int j = 0; j < 4; j++) {                                       \
                int n = wn * 32 + j * 8 + g;                                    \
                int o0 = n * GROW + (kk + 2 * q) * 2;                           \
                int o1 = n * GROW + (kk + 2 * q + 8) * 2;                       \
                bh[j][0] = *(const u32*)(sBh + o0);                             \
                bh[j][1] = *(const u32*)(sBh + o1);                             \
                bl[j][0] = *(const u32*)(sBl + o0);                             \
                bl[j][1] = *(const u32*)(sBl + o1);                             \
            }                                                                   \
            _Pragma("unroll")                                                   \
            for (int i = 0; i < 4; i++) {                                       \
                int m = wm * 64 + i * 16;                                       \
                int r0 = (m + g) * GROW;                                        \
                int r1 = (m + g + 8) * GROW;                                    \
                int c0 = (kk + 2 * q) * 2;                                      \
                int c1 = (kk + 2 * q + 8) * 2;                                  \
                u32 ah0 = *(const u32*)(sAh + r0 + c0);                         \
                u32 ah1 = *(const u32*)(sAh + r1 + c0);                         \
                u32 ah2 = *(const u32*)(sAh + r0 + c1);                         \
                u32 ah3 = *(const u32*)(sAh + r1 + c1);                         \
                u32 al0 = *(const u32*)(sAl + r0 + c0);                         \
                u32 al1 = *(const u32*)(sAl + r1 + c0);                         \
                u32 al2 = *(const u32*)(sAl + r0 + c1);                         \
                u32 al3 = *(const u32*)(sAl + r1 + c1);                         \
                _Pragma("unroll")                                               \
                for (int j = 0; j < 4; j++) {                                   \
                    mma16816(ACC[i][j], ah0, ah1, ah2, ah3, bh[j][0], bh[j][1]);\
                    mma16816(ACC[i][j], ah0, ah1, ah2, ah3, bl[j][0], bl[j][1]);\
                    mma16816(ACC[i][j], al0, al1, al2, al3, bh[j][0], bh[j][1]);\
                }                                                               \
            }                                                                   \
        }                                                                       \
        __syncthreads();                                                        \
    }

__global__ void __launch_bounds__(256) gemm_mma(
    const __nv_bfloat16* __restrict__ Ah, const __nv_bfloat16* __restrict__ Al,
    const __nv_bfloat16* __restrict__ Bh, const __nv_bfloat16* __restrict__ Bl,
    const float* __restrict__ bias, float* __restrict__ C) {
    extern __shared__ char smem[];
    float acc[4][4][4] = {};
    GEMM_BODY(acc)
    #pragma unroll
    for (int i = 0; i < 4; i++) {
        int row = m0 + wm * 64 + i * 16;
        #pragma unroll
        for (int j = 0; j < 4; j++) {
            int col = n0 + wn * 32 + j * 8 + 2 * q;
            float b0 = __ldg(bias + col);
            float b1 = __ldg(bias + col + 1);
            float2 v0 = make_float2(acc[i][j][0] + b0, acc[i][j][1] + b1);
            float2 v1 = make_float2(acc[i][j][2] + b0, acc[i][j][3] + b1);
            *(float2*)&C[(size_t)(row + g) * D_ + col]     = v0;
            *(float2*)&C[(size_t)(row + g + 8) * D_ + col] = v1;
        }
    }
}

__global__ void __launch_bounds__(256) gemm_split(
    const __nv_bfloat16* __restrict__ Ah, const __nv_bfloat16* __restrict__ Al,
    const __nv_bfloat16* __restrict__ Bh, const __nv_bfloat16* __restrict__ Bl,
    const float* __restrict__ bias,
    __nv_bfloat16* __restrict__ Ch, __nv_bfloat16* __restrict__ Cl) {
    extern __shared__ char smem[];
    float acc[4][4][4] = {};
    GEMM_BODY(acc)
    #pragma unroll
    for (int i = 0; i < 4; i++) {
        int row = m0 + wm * 64 + i * 16;
        #pragma unroll
        for (int j = 0; j < 4; j++) {
            int col = n0 + wn * 32 + j * 8 + 2 * q;
            float b0 = __ldg(bias + col);
            float b1 = __ldg(bias + col + 1);
            float vs[4] = {acc[i][j][0] + b0, acc[i][j][1] + b1,
                           acc[i][j][2] + b0, acc[i][j][3] + b1};
            u32 hb[4], lb[4];
            #pragma unroll
            for (int t = 0; t < 4; t++) {
                hb[t] = f2bf_bits(vs[t]);
                lb[t] = f2bf_bits(vs[t] - __uint_as_float(hb[t] << 16));
            }
            size_t o0 = (size_t)(row + g) * D_ + col;
            size_t o1 = (size_t)(row + g + 8) * D_ + col;
            *(u32*)&Ch[o0] = hb[0] | (hb[1] << 16);
            *(u32*)&Cl[o0] = lb[0] | (lb[1] << 16);
            *(u32*)&Ch[o1] = hb[2] | (hb[3] << 16);
            *(u32*)&Cl[o1] = lb[2] | (lb[3] << 16);
        }
    }
}

// ======================= fused attention (512 threads) =====================
#define RQ 16
#define CK 128
#define SROW 2056
#define SC_BYTES (RQ * SROW * 4)
#define KROW 144
#define KTILE (CK * KROW)
#define KSTG  (2 * KTILE)
#define KA_OFF SC_BYTES
#define Q_OFF (KA_OFF + 2 * KSTG)
#define QTILE (RQ * KROW)
#define FA_SMEM (Q_OFF + 2 * QTILE)
#define FT 512

__device__ __forceinline__ void stage_pair_chunk(
    u32 sb, const __nv_bfloat16* Xh, const __nv_bfloat16* Xl,
    int b, int h, int c, int buf, int tid) {
    #pragma unroll
    for (int i = tid; i < 2048; i += FT) {
        int which = i >> 10, j = i & 1023, row = j >> 3, sub = j & 7;
        const __nv_bfloat16* src = (which ? Xl : Xh) +
            ((size_t)b * S_ + (size_t)c * CK + row) * D_ + h * KS_ + sub * 8;
        cp_async16(sb + KA_OFF + buf * KSTG + which * KTILE + row * KROW + sub * 16, src);
    }
}

__global__ void __launch_bounds__(FT) fused_attn(
    const __nv_bfloat16* __restrict__ Qh, const __nv_bfloat16* __restrict__ Ql,
    const __nv_bfloat16* __restrict__ Kh, const __nv_bfloat16* __restrict__ Kl,
    const __nv_bfloat16* __restrict__ Vh, const __nv_bfloat16* __restrict__ Vl,
    const float* __restrict__ mask, float* __restrict__ align,
    __nv_bfloat16* __restrict__ CtxH, __nv_bfloat16* __restrict__ CtxL) {
    extern __shared__ char smem[];
    const u32 sb = smem_u32(smem);
    float* sc = (float*)smem;
    u32* scu = (u32*)smem;

    const int tid = threadIdx.x, lane = tid & 31, w = tid >> 5;  // w: 0..15
    const int g = lane >> 2, qq = lane & 3;
    const int bh = blockIdx.y, b = bh >> 4, h = bh & 15;
    const int q0 = blockIdx.x * RQ;

    // stage Q (256 cp.async)
    if (tid < 256) {
        int which = tid >> 7, j = tid & 127, row = j >> 3, sub = j & 7;
        const __nv_bfloat16* src = (which ? Ql : Qh) +
            ((size_t)b * S_ + q0 + row) * D_ + h * KS_ + sub * 8;
        cp_async16(sb + Q_OFF + which * QTILE + row * KROW + sub * 16, src);
    }
    stage_pair_chunk(sb, Kh, Kl, b, h, 0, 0, tid);
    cp_commit();

    u32 ah[4][4], al[4][4];
    const float* mrow = mask + (size_t)b * S_ * S_;

    // =================== phase 1: scores ===================
    for (int c = 0; c < 16; c++) {
        if (c + 1 < 16) {
            stage_pair_chunk(sb, Kh, Kl, b, h, c + 1, (c + 1) & 1, tid);
            cp_commit();
            cp_wait<1>();
        } else {
            cp_wait<0>();
        }
        __syncthreads();

        if (c == 0) {
            const char* sQh = smem + Q_OFF;
            const char* sQl = smem + Q_OFF + QTILE;
            #pragma unroll
            for (int ks = 0; ks < 4; ks++) {
                int c0 = (ks * 16 + 2 * qq) * 2, c1 = c0 + 16;
                ah[ks][0] = *(const u32*)(sQh + g * KROW + c0);
                ah[ks][1] = *(const u32*)(sQh + (g + 8) * KROW + c0);
                ah[ks][2] = *(const u32*)(sQh + g * KROW + c1);
                ah[ks][3] = *(const u32*)(sQh + (g + 8) * KROW + c1);
                al[ks][0] = *(const u32*)(sQl + g * KROW + c0);
                al[ks][1] = *(const u32*)(sQl + (g + 8) * KROW + c0);
                al[ks][2] = *(const u32*)(sQl + g * KROW + c1);
                al[ks][3] = *(const u32*)(sQl + (g + 8) * KROW + c1);
            }
        }

        const char* sKh = smem + KA_OFF + (c & 1) * KSTG;
        const char* sKl = sKh + KTILE;

        {
            float acc[4] = {0.f, 0.f, 0.f, 0.f};
            int nbase = w * 8;
            #pragma unroll
            for (int ks = 0; ks < 4; ks++) {
                int ko = (ks * 16 + 2 * qq) * 2;
                u32 bh0 = *(const u32*)(sKh + (nbase + g) * KROW + ko);
                u32 bh1 = *(const u32*)(sKh + (nbase + g) * KROW + ko + 16);
                u32 bl0 = *(const u32*)(sKl + (nbase + g) * KROW + ko);
                u32 bl1 = *(const u32*)(sKl + (nbase + g) * KROW + ko + 16);
                mma16816(acc, ah[ks][0], ah[ks][1], ah[ks][2], ah[ks][3], bh0, bh1);
                mma16816(acc, ah[ks][0], ah[ks][1], ah[ks][2], ah[ks][3], bl0, bl1);
                mma16816(acc, al[ks][0], al[ks][1], al[ks][2], al[ks][3], bh0, bh1);
            }
            int col = c * 128 + nbase + 2 * qq;
            int r0 = q0 + g, r1 = q0 + g + 8;
            float2 m0 = *(const float2*)&mrow[(size_t)r0 * S_ + col];
            float2 m1 = *(const float2*)&mrow[(size_t)r1 * S_ + col];
            float s0 = acc[0] * 0.125f * m0.x; if (s0 == 0.0f) s0 = NEG_BIG;
            float s1 = acc[1] * 0.125f * m0.y; if (s1 == 0.0f) s1 = NEG_BIG;
            float s2 = acc[2] * 0.125f * m1.x; if (s2 == 0.0f) s2 = NEG_BIG;
            float s3 = acc[3] * 0.125f * m1.y; if (s3 == 0.0f) s3 = NEG_BIG;
            *(float2*)&sc[g * SROW + col]       = make_float2(s0, s1);
            *(float2*)&sc[(g + 8) * SROW + col] = make_float2(s2, s3);
        }
        __syncthreads();
    }

    // prefetch V chunk 0 (hidden behind softmax; staging buffers are idle now)
    stage_pair_chunk(sb, Vh, Vl, b, h, 0, 0, tid);
    cp_commit();

    // =================== phase 2: softmax (1 row / warp) ===================
    {
        int r = w;
        float* row = sc + r * SROW;
        float mx = -3.402823466e38f;
        for (int i = lane; i < S_; i += 32) mx = fmaxf(mx, row[i]);
        #pragma unroll
        for (int o = 16; o > 0; o >>= 1) mx = fmaxf(mx, __shfl_xor_sync(0xffffffffu, mx, o));
        float sm = 0.f;
        for (int i = lane; i < S_; i += 32) {
            float e = exp_fast(row[i] - mx);
            row[i] = e;
            sm += e;
        }
        #pragma unroll
        for (int o = 16; o > 0; o >>= 1) sm += __shfl_xor_sync(0xffffffffu, sm, o);
        float inv = 1.0f / sm;
        float* arow = align + ((size_t)bh * S_ + q0 + r) * S_;
        u32* prow = (u32*)row;
        for (int i = lane; i < S_; i += 32) {
            float p = row[i] * inv;
            arow[i] = p;
            u32 hb = f2bf_bits(p);
            float res = p - __uint_as_float(hb << 16);
            prow[i] = hb | (f2bf_bits(res) << 16);
        }
    }
    __syncthreads();

    // ===== phase 3: O = P.V — one chunk/iter, all warps, double-buffered ====
    const int kd = w >> 3, wc = w & 7;     // k-half within chunk, n-col group
    float oacc[4] = {0.f, 0.f, 0.f, 0.f};
    for (int c = 0; c < 16; c++) {
        if (c + 1 < 16) {
            stage_pair_chunk(sb, Vh, Vl, b, h, c + 1, (c + 1) & 1, tid);
            cp_commit();
            cp_wait<1>();
        } else {
            cp_wait<0>();
        }
        __syncthreads();

        u32 vbase = sb + KA_OFF + (c & 1) * KSTG;
        #pragma unroll
        for (int ksl = 0; ksl < 4; ksl++) {
            int ks = kd * 4 + ksl;                       // 0..7 within chunk
            int k0 = c * 128 + ks * 16 + 2 * qq;
            uint2 w0 = *(const uint2*)&scu[g * SROW + k0];
            uint2 w1 = *(const uint2*)&scu[g * SROW + k0 + 8];
            uint2 w2 = *(const uint2*)&scu[(g + 8) * SROW + k0];
            uint2 w3 = *(const uint2*)&scu[(g + 8) * SROW + k0 + 8];
            u32 pah0 = prmt(w0.x, w0.y, 0x5410), pal0 = prmt(w0.x, w0.y, 0x7632);
            u32 pah1 = prmt(w2.x, w2.y, 0x5410), pal1 = prmt(w2.x, w2.y, 0x7632);
            u32 pah2 = prmt(w1.x, w1.y, 0x5410), pal2 = prmt(w1.x, w1.y, 0x7632);
            u32 pah3 = prmt(w3.x, w3.y, 0x5410), pal3 = prmt(w3.x, w3.y, 0x7632);

            u32 addr = vbase + (ks * 16 + (lane & 15)) * KROW + wc * 16;
            u32 vbh0, vbh1, vbl0, vbl1;
            ldsm_x2_t(vbh0, vbh1, addr);
            ldsm_x2_t(vbl0, vbl1, addr + KTILE);

            mma16816(oacc, pah0, pah1, pah2, pah3, vbh0, vbh1);
            mma16816(oacc, pah0, pah1, pah2, pah3, vbl0, vbl1);
            mma16816(oacc, pal0, pal1, pal2, pal3, vbh0, vbh1);
        }
        __syncthreads();
    }

    // reduce k-halves: kd=1 warps store partials, kd=0 adds + writes bf16 split
    float* red = (float*)(smem + Q_OFF);
    if (kd == 1) {
        float4* dst = (float4*)red;
        dst[(w - 8) * 32 + lane] = make_float4(oacc[0], oacc[1], oacc[2], oacc[3]);
    }
    __syncthreads();
    if (kd == 0) {
        float4 pp = ((float4*)red)[w * 32 + lane];
        oacc[0] += pp.x; oacc[1] += pp.y; oacc[2] += pp.z; oacc[3] += pp.w;
        int col = h * KS_ + wc * 8 + 2 * qq;
        size_t o0 = ((size_t)b * S_ + q0 + g) * D_ + col;
        size_t o1 = o0 + 8 * D_;
        u32 hb0 = f2bf_bits(oacc[0]), hb1 = f2bf_bits(oacc[1]);
        u32 hb2 = f2bf_bits(oacc[2]), hb3 = f2bf_bits(oacc[3]);
        u32 lb0 = f2bf_bits(oacc[0] - __uint_as_float(hb0 << 16));
        u32 lb1 = f2bf_bits(oacc[1] - __uint_as_float(hb1 << 16));
        u32 lb2 = f2bf_bits(oacc[2] - __uint_as_float(hb2 << 16));
        u32 lb3 = f2bf_bits(oacc[3] - __uint_as_float(hb3 << 16));
        *(u32*)&CtxH[o0] = hb0 | (hb1 << 16);
        *(u32*)&CtxL[o0] = lb0 | (lb1 << 16);
        *(u32*)&CtxH[o1] = hb2 | (hb3 << 16);
        *(u32*)&CtxL[o1] = lb2 | (lb3 << 16);
    }
}

// ---------------------------------------------------------------------------
extern "C" void kernel_launch(void* const* d_in, const int* in_sizes, int n_in,
                              void* d_out, int out_size) {
    const float* q    = (const float*)d_in[0];
    const float* v    = (const float*)d_in[1];
    const float* mask = (const float*)d_in[2];
    const float* wq_w = (const float*)d_in[3];
    const float* wq_b = (const float*)d_in[4];
    const float* wk_w = (const float*)d_in[5];
    const float* wk_b = (const float*)d_in[6];
    const float* wv_w = (const float*)d_in[7];
    const float* wv_b = (const float*)d_in[8];
    const float* wo_w = (const float*)d_in[9];
    const float* wo_b = (const float*)d_in[10];

    float* out = (float*)d_out;
    float* heads = out;
    float* align = out + NTOK;

    float* scratch = nullptr;
    cudaGetSymbolAddress((void**)&scratch, g_scratch);

    __nv_bfloat16* AqH = (__nv_bfloat16*)(scratch + 0 * F_ACT);
    __nv_bfloat16* AqL = (__nv_bfloat16*)(scratch + 1 * F_ACT);
    __nv_bfloat16* AvH = (__nv_bfloat16*)(scratch + 2 * F_ACT);
    __nv_bfloat16* AvL = (__nv_bfloat16*)(scratch + 3 * F_ACT);
    __nv_bfloat16* QsH = (__nv_bfloat16*)(scratch + 4 * F_ACT);
    __nv_bfloat16* QsL = (__nv_bfloat16*)(scratch + 5 * F_ACT);
    __nv_bfloat16* KsH = (__nv_bfloat16*)(scratch + 6 * F_ACT);
    __nv_bfloat16* KsL = (__nv_bfloat16*)(scratch + 7 * F_ACT);
    __nv_bfloat16* VsH = (__nv_bfloat16*)(scratch + 8 * F_ACT);
    __nv_bfloat16* VsL = (__nv_bfloat16*)(scratch + 9 * F_ACT);
    float* wb = scratch + 10 * F_ACT;
    __nv_bfloat16* WqH = (__nv_bfloat16*)(wb + 0 * F_W);
    __nv_bfloat16* WqL = (__nv_bfloat16*)(wb + 1 * F_W);
    __nv_bfloat16* WkH = (__nv_bfloat16*)(wb + 2 * F_W);
    __nv_bfloat16* WkL = (__nv_bfloat16*)(wb + 3 * F_W);
    __nv_bfloat16* WvH = (__nv_bfloat16*)(wb + 4 * F_W);
    __nv_bfloat16* WvL = (__nv_bfloat16*)(wb + 5 * F_W);
    __nv_bfloat16* WoH = (__nv_bfloat16*)(wb + 6 * F_W);
    __nv_bfloat16* WoL = (__nv_bfloat16*)(wb + 7 * F_W);

    cudaFuncSetAttribute(gemm_mma, cudaFuncAttributeMaxDynamicSharedMemorySize, GSMEM);
    cudaFuncSetAttribute(gemm_split, cudaFuncAttributeMaxDynamicSharedMemorySize, GSMEM);
    cudaFuncSetAttribute(fused_attn, cudaFuncAttributeMaxDynamicSharedMemorySize, FA_SMEM);

    int nAct = (int)NTOK;
    int gA = (nAct / 4 + 255) / 256;

    conv_w4<<<dim3(32, 32, 4), dim3(32, 8)>>>(wq_w, wk_w, wv_w, wo_w,
                                              WqH, WqL, WkH, WkL,
                                              WvH, WvL, WoH, WoL);
    conv_act<<<gA, 256>>>(q, AqH, AqL, nAct);
    conv_act<<<gA, 256>>>(v, AvH, AvL, nAct);

    dim3 gproj(D_ / 128, (B_ * S_) / 128);
    gemm_split<<<gproj, 256, GSMEM>>>(AqH, AqL, WqH, WqL, wq_b, QsH, QsL);
    gemm_split<<<gproj, 256, GSMEM>>>(AvH, AvL, WkH, WkL, wk_b, KsH, KsL);
    gemm_split<<<gproj, 256, GSMEM>>>(AvH, AvL, WvH, WvL, wv_b, VsH, VsL);

    dim3 gfa(S_ / RQ, B_ * H_);
    fused_attn<<<gfa, FT, FA_SMEM>>>(QsH, QsL, KsH, KsL, VsH, VsL,
                                     mask, align, AqH, AqL);

    gemm_mma<<<gproj, 256, GSMEM>>>(AqH, AqL, WoH, WoL, wo_b, heads);
}

// round 11
// speedup vs baseline: 2.1072x; 1.2806x over previous
#include <cuda_runtime.h>
#include <cuda_bf16.h>
#include <cstdint>

#define B_  2
#define S_  2048
#define D_  1024
#define H_  16
#define KS_ 64
#define NEG_BIG (-1.0e9f)

#define NTOK ((size_t)B_ * S_ * D_)

#define F_ACT   (NTOK / 2)            // float slots per bf16 [B,S,D] array
#define F_W     ((size_t)D_ * D_ / 2)
__device__ __align__(16) float g_scratch[10 * F_ACT + 8 * F_W];

typedef uint32_t u32;

// ============================ helpers ======================================
__device__ __forceinline__ u32 smem_u32(const void* p) {
    u32 a;
    asm("{ .reg .u64 t; cvta.to.shared.u64 t, %1; cvt.u32.u64 %0, t; }"
        : "=r"(a) : "l"(p));
    return a;
}
__device__ __forceinline__ void cp_async16(u32 saddr, const void* gaddr) {
    asm volatile("cp.async.cg.shared.global [%0], [%1], 16;"
                 :: "r"(saddr), "l"(gaddr) : "memory");
}
__device__ __forceinline__ void cp_commit() {
    asm volatile("cp.async.commit_group;" ::: "memory");
}
template <int N>
__device__ __forceinline__ void cp_wait() {
    asm volatile("cp.async.wait_group %0;" :: "n"(N) : "memory");
}
__device__ __forceinline__ void mma16816(float* d, u32 a0, u32 a1,
                                         u32 a2, u32 a3, u32 b0, u32 b1) {
    asm volatile(
        "mma.sync.aligned.m16n8k16.row.col.f32.bf16.bf16.f32 "
        "{%0,%1,%2,%3}, {%4,%5,%6,%7}, {%8,%9}, {%0,%1,%2,%3};"
        : "+f"(d[0]), "+f"(d[1]), "+f"(d[2]), "+f"(d[3])
        : "r"(a0), "r"(a1), "r"(a2), "r"(a3), "r"(b0), "r"(b1));
}
__device__ __forceinline__ void ldsm_x2_t(u32& r0, u32& r1, u32 a) {
    asm volatile("ldmatrix.sync.aligned.m8n8.x2.trans.shared.b16 {%0,%1}, [%2];"
                 : "=r"(r0), "=r"(r1) : "r"(a));
}
__device__ __forceinline__ u32 f2bf_bits(float x) {
    u32 u = __float_as_uint(x);
    return (u + 0x7FFFu + ((u >> 16) & 1u)) >> 16;
}
__device__ __forceinline__ float exp_fast(float x) {
    x = fmaxf(x, -87.3f);
    float y = x * 1.44269504089f;
    float n = rintf(y);
    float f = y - n;
    float p = 1.33336498402e-3f;
    p = fmaf(p, f, 9.61793571616e-3f);
    p = fmaf(p, f, 5.55043442248e-2f);
    p = fmaf(p, f, 2.40226506959e-1f);
    p = fmaf(p, f, 6.93147180560e-1f);
    p = fmaf(p, f, 1.0f);
    return __int_as_float(__float_as_int(p) + (((int)n) << 23));
}

// ======================= conversion kernels ================================
__global__ void conv_act(const float* __restrict__ x,
                         __nv_bfloat16* __restrict__ h,
                         __nv_bfloat16* __restrict__ l, int n) {
    int i = blockIdx.x * blockDim.x + threadIdx.x;
    int i4 = i * 4;
    if (i4 >= n) return;
    float4 v = *(const float4*)(x + i4);
    float vs[4] = {v.x, v.y, v.z, v.w};
    __nv_bfloat16 hh[4], ll[4];
    #pragma unroll
    for (int j = 0; j < 4; j++) {
        __nv_bfloat16 hi = __float2bfloat16_rn(vs[j]);
        float r = vs[j] - __bfloat162float(hi);
        hh[j] = hi;
        ll[j] = __float2bfloat16_rn(r);
    }
    __nv_bfloat162* H2 = (__nv_bfloat162*)(h + i4);
    __nv_bfloat162* L2 = (__nv_bfloat162*)(l + i4);
    H2[0] = __nv_bfloat162(hh[0], hh[1]);
    H2[1] = __nv_bfloat162(hh[2], hh[3]);
    L2[0] = __nv_bfloat162(ll[0], ll[1]);
    L2[1] = __nv_bfloat162(ll[2], ll[3]);
}

__global__ void conv_w4(const float* __restrict__ W0, const float* __restrict__ W1,
                        const float* __restrict__ W2, const float* __restrict__ W3,
                        __nv_bfloat16* __restrict__ T0h, __nv_bfloat16* __restrict__ T0l,
                        __nv_bfloat16* __restrict__ T1h, __nv_bfloat16* __restrict__ T1l,
                        __nv_bfloat16* __restrict__ T2h, __nv_bfloat16* __restrict__ T2l,
                        __nv_bfloat16* __restrict__ T3h, __nv_bfloat16* __restrict__ T3l) {
    __shared__ float t[32][33];
    const float* W;
    __nv_bfloat16 *Th, *Tl;
    switch (blockIdx.z) {
        case 0: W = W0; Th = T0h; Tl = T0l; break;
        case 1: W = W1; Th = T1h; Tl = T1l; break;
        case 2: W = W2; Th = T2h; Tl = T2l; break;
        default: W = W3; Th = T3h; Tl = T3l; break;
    }
    int n0 = blockIdx.x * 32, k0 = blockIdx.y * 32;
    int tx = threadIdx.x, ty = threadIdx.y;
    for (int r = ty; r < 32; r += 8)
        t[r][tx] = W[(size_t)(k0 + r) * D_ + n0 + tx];
    __syncthreads();
    for (int r = ty; r < 32; r += 8) {
        float x = t[tx][r];
        __nv_bfloat16 hi = __float2bfloat16_rn(x);
        float res = x - __bfloat162float(hi);
        size_t o = (size_t)(n0 + r) * D_ + k0 + tx;
        Th[o] = hi;
        Tl[o] = __float2bfloat16_rn(res);
    }
}

// ======================= HMMA GEMM core (R5-verified) ======================
#define GROW   80
#define GTILE  (128 * GROW)
#define GSTAGE (4 * GTILE)
#define GSMEM  (2 * GSTAGE)

#define GEMM_BODY(ACC)                                                          \
    const u32 sb = smem_u32(smem);                                              \
    const int tid  = threadIdx.x;                                               \
    const int lane = tid & 31;                                                  \
    const int wid  = tid >> 5;                                                  \
    const int wm   = wid >> 2;                                                  \
    const int wn   = wid & 3;                                                   \
    const int g    = lane >> 2;                                                 \
    const int q    = lane & 3;                                                  \
    const int n0 = blockIdx.x * 128;                                            \
    const int m0 = blockIdx.y * 128;                                            \
    const int cid0 = tid * 2;                                                   \
    const int row0 = cid0 >> 2;                                                 \
    const int cc0  = (cid0 & 3) * 8;                                            \
    const int row1 = (cid0 + 1) >> 2;                                           \
    const int cc1  = ((cid0 + 1) & 3) * 8;                                      \
    const int NK = D_ / 32;                                                     \
    {                                                                           \
        u32 s = sb;                                                             \
        cp_async16(s + 0 * GTILE + row0 * GROW + (cc0 & 31) * 2, Ah + (size_t)(m0 + row0) * D_ + cc0); \
        cp_async16(s + 0 * GTILE + row1 * GROW + (cc1 & 31) * 2, Ah + (size_t)(m0 + row1) * D_ + cc1); \
        cp_async16(s + 1 * GTILE + row0 * GROW + (cc0 & 31) * 2, Al + (size_t)(m0 + row0) * D_ + cc0); \
        cp_async16(s + 1 * GTILE + row1 * GROW + (cc1 & 31) * 2, Al + (size_t)(m0 + row1) * D_ + cc1); \
        cp_async16(s + 2 * GTILE + row0 * GROW + (cc0 & 31) * 2, Bh + (size_t)(n0 + row0) * D_ + cc0); \
        cp_async16(s + 2 * GTILE + row1 * GROW + (cc1 & 31) * 2, Bh + (size_t)(n0 + row1) * D_ + cc1); \
        cp_async16(s + 3 * GTILE + row0 * GROW + (cc0 & 31) * 2, Bl + (size_t)(n0 + row0) * D_ + cc0); \
        cp_async16(s + 3 * GTILE + row1 * GROW + (cc1 & 31) * 2, Bl + (size_t)(n0 + row1) * D_ + cc1); \
        cp_commit();                                                            \
    }                                                                           \
    for (int ks = 0; ks < NK; ks++) {                                           \
        if (ks + 1 < NK) {                                                      \
            int k0 = (ks + 1) * 32;                                             \
            u32 s = sb + ((ks + 1) & 1) * GSTAGE;                               \
            cp_async16(s + 0 * GTILE + row0 * GROW + (cc0 & 31) * 2, Ah + (size_t)(m0 + row0) * D_ + k0 + cc0); \
            cp_async16(s + 0 * GTILE + row1 * GROW + (cc1 & 31) * 2, Ah + (size_t)(m0 + row1) * D_ + k0 + cc1); \
            cp_async16(s + 1 * GTILE + row0 * GROW + (cc0 & 31) * 2, Al + (size_t)(m0 + row0) * D_ + k0 + cc0); \
            cp_async16(s + 1 * GTILE + row1 * GROW + (cc1 & 31) * 2, Al + (size_t)(m0 + row1) * D_ + k0 + cc1); \
            cp_async16(s + 2 * GTILE + row0 * GROW + (cc0 & 31) * 2, Bh + (size_t)(n0 + row0) * D_ + k0 + cc0); \
            cp_async16(s + 2 * GTILE + row1 * GROW + (cc1 & 31) * 2, Bh + (size_t)(n0 + row1) * D_ + k0 + cc1); \
            cp_async16(s + 3 * GTILE + row0 * GROW + (cc0 & 31) * 2, Bl + (size_t)(n0 + row0) * D_ + k0 + cc0); \
            cp_async16(s + 3 * GTILE + row1 * GROW + (cc1 & 31) * 2, Bl + (size_t)(n0 + row1) * D_ + k0 + cc1); \
            cp_commit();                                                        \
            cp_wait<1>();                                                       \
        } else {                                                                \
            cp_wait<0>();                                                       \
        }                                                                       \
        __syncthreads();                                                        \
        const char* st  = smem + (ks & 1) * GSTAGE;                             \
        const char* sAh = st;                                                   \
        const char* sAl = st + GTILE;                                           \
        const char* sBh = st + 2 * GTILE;                                       \
        const char* sBl = st + 3 * GTILE;                                       \
        _Pragma("unroll")                                                       \
        for (int kk = 0; kk < 32; kk += 16) {                                   \
            u32 bh[4][2], bl[4][2];                                             \
            _Pragma("unroll")                                                   \
            for (int j = 0; j < 4; j++) {                                       \
                int n = wn * 32 + j * 8 + g;                                    \
                int o0 = n * GROW + (kk + 2 * q) * 2;                           \
                int o1 = n * GROW + (kk + 2 * q + 8) * 2;                       \
                bh[j][0] = *(const u32*)(sBh + o0);                             \
                bh[j][1] = *(const u32*)(sBh + o1);                             \
                bl[j][0] = *(const u32*)(sBl + o0);                             \
                bl[j][1] = *(const u32*)(sBl + o1);                             \
            }                                                                   \
            _Pragma("unroll")                                                   \
            for (int i = 0; i < 4; i++) {                                       \
                int m = wm * 64 + i * 16;                                       \
                int r0 = (m + g) * GROW;                                        \
                int r1 = (m + g + 8) * GROW;                                    \
                int c0 = (kk + 2 * q) * 2;                                      \
                int c1 = (kk + 2 * q + 8) * 2;                                  \
                u32 ah0 = *(const u32*)(sAh + r0 + c0);                         \
                u32 ah1 = *(const u32*)(sAh + r1 + c0);                         \
                u32 ah2 = *(const u32*)(sAh + r0 + c1);                         \
                u32 ah3 = *(const u32*)(sAh + r1 + c1);                         \
                u32 al0 = *(const u32*)(sAl + r0 + c0);                         \
                u32 al1 = *(const u32*)(sAl + r1 + c0);                         \
                u32 al2 = *(const u32*)(sAl + r0 + c1);                         \
                u32 al3 = *(const u32*)(sAl + r1 + c1);                         \
                _Pragma("unroll")                                               \
                for (int j = 0; j < 4; j++) {                                   \
                    mma16816(ACC[i][j], ah0, ah1, ah2, ah3, bh[j][0], bh[j][1]);\
                    mma16816(ACC[i][j], ah0, ah1, ah2, ah3, bl[j][0], bl[j][1]);\
                    mma16816(ACC[i][j], al0, al1, al2, al3, bh[j][0], bh[j][1]);\
                }                                                               \
            }                                                                   \
        }                                                                       \
        __syncthreads();                                                        \
    }

__global__ void __launch_bounds__(256) gemm_mma(
    const __nv_bfloat16* __restrict__ Ah, const __nv_bfloat16* __restrict__ Al,
    const __nv_bfloat16* __restrict__ Bh, const __nv_bfloat16* __restrict__ Bl,
    const float* __restrict__ bias, float* __restrict__ C) {
    extern __shared__ char smem[];
    float acc[4][4][4] = {};
    GEMM_BODY(acc)
    #pragma unroll
    for (int i = 0; i < 4; i++) {
        int row = m0 + wm * 64 + i * 16;
        #pragma unroll
        for (int j = 0; j < 4; j++) {
            int col = n0 + wn * 32 + j * 8 + 2 * q;
            float b0 = __ldg(bias + col);
            float b1 = __ldg(bias + col + 1);
            float2 v0 = make_float2(acc[i][j][0] + b0, acc[i][j][1] + b1);
            float2 v1 = make_float2(acc[i][j][2] + b0, acc[i][j][3] + b1);
            *(float2*)&C[(size_t)(row + g) * D_ + col]     = v0;
            *(float2*)&C[(size_t)(row + g + 8) * D_ + col] = v1;
        }
    }
}

__global__ void __launch_bounds__(256) gemm_split(
    const __nv_bfloat16* __restrict__ Ah, const __nv_bfloat16* __restrict__ Al,
    const __nv_bfloat16* __restrict__ Bh, const __nv_bfloat16* __restrict__ Bl,
    const float* __restrict__ bias,
    __nv_bfloat16* __restrict__ Ch, __nv_bfloat16* __restrict__ Cl) {
    extern __shared__ char smem[];
    float acc[4][4][4] = {};
    GEMM_BODY(acc)
    #pragma unroll
    for (int i = 0; i < 4; i++) {
        int row = m0 + wm * 64 + i * 16;
        #pragma unroll
        for (int j = 0; j < 4; j++) {
            int col = n0 + wn * 32 + j * 8 + 2 * q;
            float b0 = __ldg(bias + col);
            float b1 = __ldg(bias + col + 1);
            float vs[4] = {acc[i][j][0] + b0, acc[i][j][1] + b1,
                           acc[i][j][2] + b0, acc[i][j][3] + b1};
            u32 hb[4], lb[4];
            #pragma unroll
            for (int t = 0; t < 4; t++) {
                hb[t] = f2bf_bits(vs[t]);
                lb[t] = f2bf_bits(vs[t] - __uint_as_float(hb[t] << 16));
            }
            size_t o0 = (size_t)(row + g) * D_ + col;
            size_t o1 = (size_t)(row + g + 8) * D_ + col;
            *(u32*)&Ch[o0] = hb[0] | (hb[1] << 16);
            *(u32*)&Cl[o0] = lb[0] | (lb[1] << 16);
            *(u32*)&Ch[o1] = hb[2] | (hb[3] << 16);
            *(u32*)&Cl[o1] = lb[2] | (lb[3] << 16);
        }
    }
}

// ======================= flash attention (512 threads) =====================
// Block = 64 q-rows x one (b,h). K/V streamed in 128-row chunks, double-buffered.
// Online softmax; align written UNNORMALIZED (exp(s - m_running)); fixup kernel
// rescales by exp(m_used - m_final)/sum afterward. Context accumulated with
// per-chunk O rescale; P fragments packed in registers (no score smem at all).
#define QT 64
#define NCH 16
#define KROW 144
#define CTILE (128 * KROW)                 // 18432 (one plane)
#define CSTG  (2 * CTILE)                  // 36864 (hi+lo)
#define KB_OFF 0                           // 2 bufs: 73728
#define VB_OFF (2 * CSTG)                  // 73728..147456
#define QB_OFF (4 * CSTG)                  // 147456; Q hi/lo = 18432
#define ST_OFF (QB_OFF + 2 * QT * KROW)    // 165888
#define FL_SMEM (ST_OFF + 4096)            // 169984
#define FT 512

__device__ __forceinline__ void fl_stage(u32 dst, const __nv_bfloat16* Xh,
                                         const __nv_bfloat16* Xl,
                                         int b, int h, int c, int tid) {
    #pragma unroll
    for (int i = tid; i < 2048; i += FT) {
        int which = i >> 10, j = i & 1023, row = j >> 3, sub = j & 7;
        const __nv_bfloat16* src = (which ? Xl : Xh) +
            ((size_t)b * S_ + (size_t)c * 128 + row) * D_ + h * KS_ + sub * 8;
        cp_async16(dst + which * CTILE + row * KROW + sub * 16, src);
    }
}

__global__ void __launch_bounds__(FT, 1) flash_attn(
    const __nv_bfloat16* __restrict__ Qh, const __nv_bfloat16* __restrict__ Ql,
    const __nv_bfloat16* __restrict__ Kh, const __nv_bfloat16* __restrict__ Kl,
    const __nv_bfloat16* __restrict__ Vh, const __nv_bfloat16* __restrict__ Vl,
    const float* __restrict__ mask, float* __restrict__ align,
    float* __restrict__ mu, float* __restrict__ mfin, float* __restrict__ isv,
    __nv_bfloat16* __restrict__ CtxH, __nv_bfloat16* __restrict__ CtxL) {
    extern __shared__ char smem[];
    const u32 sb = smem_u32(smem);

    const int tid = threadIdx.x, lane = tid & 31, w = tid >> 5;
    const int g = lane >> 2, qq = lane & 3;
    const int wr = w >> 2, wc = w & 3;            // 4x4 warp grid
    const int bh = blockIdx.y, b = bh >> 4, h = bh & 15;
    const int q0 = blockIdx.x * QT;

    // stage Q (1024 cp.async) + K0 + V0
    #pragma unroll
    for (int i = tid; i < 1024; i += FT) {
        int which = i >> 9, j = i & 511, row = j >> 3, sub = j & 7;
        const __nv_bfloat16* src = (which ? Ql : Qh) +
            ((size_t)b * S_ + q0 + row) * D_ + h * KS_ + sub * 8;
        cp_async16(sb + QB_OFF + which * (QT * KROW) + row * KROW + sub * 16, src);
    }
    fl_stage(sb + KB_OFF, Kh, Kl, b, h, 0, tid);
    fl_stage(sb + VB_OFF, Vh, Vl, b, h, 0, tid);
    cp_commit();

    float* m_state = (float*)(smem + ST_OFF);     // [64]
    float* s_state = m_state + 64;                // [64]
    float* scalef  = s_state + 64;                // [64]
    float* pmax    = scalef + 64;                 // [4][64]
    float* psum    = pmax + 256;                  // [4][64]
    if (tid < 64) { m_state[tid] = -3.0e38f; s_state[tid] = 0.0f; }

    u32 ahq[4][4], alq[4][4];
    float oacc[8][4] = {};
    const float* mrow = mask + (size_t)b * S_ * S_;
    const int rloc0 = wr * 16 + g;                // local row of this thread
    const int rloc1 = rloc0 + 8;

    for (int c = 0; c < NCH; c++) {
        if (c + 1 < NCH) {
            u32 boff = ((c + 1) & 1) * CSTG;
            fl_stage(sb + KB_OFF + boff, Kh, Kl, b, h, c + 1, tid);
            fl_stage(sb + VB_OFF + boff, Vh, Vl, b, h, c + 1, tid);
            cp_commit();
            cp_wait<1>();
        } else {
            cp_wait<0>();
        }
        __syncthreads();                           // S1

        if (c == 0) {
            const char* sQh = smem + QB_OFF;
            const char* sQl = sQh + QT * KROW;
            #pragma unroll
            for (int ks = 0; ks < 4; ks++) {
                int r0 = rloc0 * KROW, r1 = rloc1 * KROW;
                int c0 = (ks * 16 + 2 * qq) * 2, c1 = c0 + 16;
                ahq[ks][0] = *(const u32*)(sQh + r0 + c0);
                ahq[ks][1] = *(const u32*)(sQh + r1 + c0);
                ahq[ks][2] = *(const u32*)(sQh + r0 + c1);
                ahq[ks][3] = *(const u32*)(sQh + r1 + c1);
                alq[ks][0] = *(const u32*)(sQl + r0 + c0);
                alq[ks][1] = *(const u32*)(sQl + r1 + c0);
                alq[ks][2] = *(const u32*)(sQl + r0 + c1);
                alq[ks][3] = *(const u32*)(sQl + r1 + c1);
            }
        }

        // ---- scores: warp covers 16q x 32k (4 n-blocks of 8) ----
        const char* sKh = smem + KB_OFF + (c & 1) * CSTG;
        const char* sKl = sKh + CTILE;
        float sacc[4][4] = {};
        #pragma unroll
        for (int ks = 0; ks < 4; ks++) {
            #pragma unroll
            for (int nb = 0; nb < 4; nb++) {
                int krow = (wc * 32 + nb * 8 + g) * KROW;
                int ko = (ks * 16 + 2 * qq) * 2;
                u32 b0 = *(const u32*)(sKh + krow + ko);
                u32 b1 = *(const u32*)(sKh + krow + ko + 16);
                u32 l0 = *(const u32*)(sKl + krow + ko);
                u32 l1 = *(const u32*)(sKl + krow + ko + 16);
                mma16816(sacc[nb], ahq[ks][0], ahq[ks][1], ahq[ks][2], ahq[ks][3], b0, b1);
                mma16816(sacc[nb], ahq[ks][0], ahq[ks][1], ahq[ks][2], ahq[ks][3], l0, l1);
                mma16816(sacc[nb], alq[ks][0], alq[ks][1], alq[ks][2], alq[ks][3], b0, b1);
            }
        }

        // ---- mask + scale + chunk max ----
        float mx0 = -3.0e38f, mx1 = -3.0e38f;
        #pragma unroll
        for (int nb = 0; nb < 4; nb++) {
            int col = c * 128 + wc * 32 + nb * 8 + 2 * qq;
            float2 m0 = *(const float2*)&mrow[(size_t)(q0 + rloc0) * S_ + col];
            float2 m1 = *(const float2*)&mrow[(size_t)(q0 + rloc1) * S_ + col];
            float s0 = sacc[nb][0] * 0.125f * m0.x; if (s0 == 0.0f) s0 = NEG_BIG;
            float s1 = sacc[nb][1] * 0.125f * m0.y; if (s1 == 0.0f) s1 = NEG_BIG;
            float s2 = sacc[nb][2] * 0.125f * m1.x; if (s2 == 0.0f) s2 = NEG_BIG;
            float s3 = sacc[nb][3] * 0.125f * m1.y; if (s3 == 0.0f) s3 = NEG_BIG;
            sacc[nb][0] = s0; sacc[nb][1] = s1; sacc[nb][2] = s2; sacc[nb][3] = s3;
            mx0 = fmaxf(mx0, fmaxf(s0, s1));
            mx1 = fmaxf(mx1, fmaxf(s2, s3));
        }
        mx0 = fmaxf(mx0, __shfl_xor_sync(0xffffffffu, mx0, 1));
        mx0 = fmaxf(mx0, __shfl_xor_sync(0xffffffffu, mx0, 2));
        mx1 = fmaxf(mx1, __shfl_xor_sync(0xffffffffu, mx1, 1));
        mx1 = fmaxf(mx1, __shfl_xor_sync(0xffffffffu, mx1, 2));
        if (qq == 0) {
            pmax[wc * 64 + rloc0] = mx0;
            pmax[wc * 64 + rloc1] = mx1;
        }
        __syncthreads();                           // S2

        if (tid < 64) {
            float mch = fmaxf(fmaxf(pmax[tid], pmax[64 + tid]),
                              fmaxf(pmax[128 + tid], pmax[192 + tid]));
            float mold = m_state[tid];
            float mnew = fmaxf(mold, mch);
            float f = exp_fast(mold - mnew);
            scalef[tid] = f;
            m_state[tid] = mnew;
            s_state[tid] *= f;
            mu[((size_t)bh * S_ + q0 + tid) * NCH + c] = mnew;
        }
        __syncthreads();                           // S3

        // ---- probs + align write + pack P frags + partial sums ----
        float mn0 = m_state[rloc0], mn1 = m_state[rloc1];
        float ps0 = 0.f, ps1 = 0.f;
        u32 pah[2][4], pal[2][4];
        #pragma unroll
        for (int nb = 0; nb < 4; nb++) {
            float p0 = exp_fast(sacc[nb][0] - mn0);
            float p1 = exp_fast(sacc[nb][1] - mn0);
            float p2 = exp_fast(sacc[nb][2] - mn1);
            float p3 = exp_fast(sacc[nb][3] - mn1);
            ps0 += p0 + p1; ps1 += p2 + p3;
            int col = c * 128 + wc * 32 + nb * 8 + 2 * qq;
            *(float2*)&align[((size_t)bh * S_ + q0 + rloc0) * S_ + col] = make_float2(p0, p1);
            *(float2*)&align[((size_t)bh * S_ + q0 + rloc1) * S_ + col] = make_float2(p2, p3);
            u32 hb0 = f2bf_bits(p0), hb1 = f2bf_bits(p1);
            u32 hb2 = f2bf_bits(p2), hb3 = f2bf_bits(p3);
            u32 lb0 = f2bf_bits(p0 - __uint_as_float(hb0 << 16));
            u32 lb1 = f2bf_bits(p1 - __uint_as_float(hb1 << 16));
            u32 lb2 = f2bf_bits(p2 - __uint_as_float(hb2 << 16));
            u32 lb3 = f2bf_bits(p3 - __uint_as_float(hb3 << 16));
            int kf = nb >> 1, sl = (nb & 1) * 2;
            pah[kf][sl + 0] = hb0 | (hb1 << 16);
            pah[kf][sl + 1] = hb2 | (hb3 << 16);
            pal[kf][sl + 0] = lb0 | (lb1 << 16);
            pal[kf][sl + 1] = lb2 | (lb3 << 16);
        }
        ps0 += __shfl_xor_sync(0xffffffffu, ps0, 1);
        ps0 += __shfl_xor_sync(0xffffffffu, ps0, 2);
        ps1 += __shfl_xor_sync(0xffffffffu, ps1, 1);
        ps1 += __shfl_xor_sync(0xffffffffu, ps1, 2);
        if (qq == 0) {
            psum[wc * 64 + rloc0] = ps0;
            psum[wc * 64 + rloc1] = ps1;
        }

        // ---- O rescale + PV (warp accumulates its 32-k slice) ----
        float f0 = scalef[rloc0], f1 = scalef[rloc1];
        #pragma unroll
        for (int nb2 = 0; nb2 < 8; nb2++) {
            oacc[nb2][0] *= f0; oacc[nb2][1] *= f0;
            oacc[nb2][2] *= f1; oacc[nb2][3] *= f1;
        }
        u32 vb = sb + VB_OFF + (c & 1) * CSTG;
        #pragma unroll
        for (int kf = 0; kf < 2; kf++) {
            u32 vaddr = vb + (wc * 32 + kf * 16 + (lane & 15)) * KROW;
            #pragma unroll
            for (int nb2 = 0; nb2 < 8; nb2++) {
                u32 vh0, vh1, vl0, vl1;
                ldsm_x2_t(vh0, vh1, vaddr + nb2 * 16);
                ldsm_x2_t(vl0, vl1, vaddr + nb2 * 16 + CTILE);
                mma16816(oacc[nb2], pah[kf][0], pah[kf][1], pah[kf][2], pah[kf][3], vh0, vh1);
                mma16816(oacc[nb2], pah[kf][0], pah[kf][1], pah[kf][2], pah[kf][3], vl0, vl1);
                mma16816(oacc[nb2], pal[kf][0], pal[kf][1], pal[kf][2], pal[kf][3], vh0, vh1);
            }
        }
        __syncthreads();                           // S4 (psum done; buffers free)
        if (tid < 64)
            s_state[tid] += psum[tid] + psum[64 + tid] + psum[128 + tid] + psum[192 + tid];
    }

    // ---- finalize stats ----
    if (tid < 64) {
        size_t R = (size_t)bh * S_ + q0 + tid;
        float inv = 1.0f / s_state[tid];
        mfin[R] = m_state[tid];
        isv[R] = inv;
        scalef[tid] = inv;
    }
    __syncthreads();

    // ---- reduce O across 4 warp-cols (reuse K/V smem area) ----
    float* part = (float*)smem;                    // 3 planes of 64x64
    if (wc > 0) {
        float* pl = part + (wc - 1) * 4096;
        #pragma unroll
        for (int nb2 = 0; nb2 < 8; nb2++) {
            int cc = nb2 * 8 + 2 * qq;
            *(float2*)&pl[rloc0 * 64 + cc] = make_float2(oacc[nb2][0], oacc[nb2][1]);
            *(float2*)&pl[rloc1 * 64 + cc] = make_float2(oacc[nb2][2], oacc[nb2][3]);
        }
    }
    __syncthreads();
    if (wc == 0) {
        float i0 = scalef[rloc0], i1 = scalef[rloc1];
        #pragma unroll
        for (int nb2 = 0; nb2 < 8; nb2++) {
            int cc = nb2 * 8 + 2 * qq;
            float2 a0 = *(const float2*)&part[rloc0 * 64 + cc];
            float2 b0 = *(const float2*)&part[4096 + rloc0 * 64 + cc];
            float2 c0 = *(const float2*)&part[8192 + rloc0 * 64 + cc];
            float2 a1 = *(const float2*)&part[rloc1 * 64 + cc];
            float2 b1 = *(const float2*)&part[4096 + rloc1 * 64 + cc];
            float2 c1 = *(const float2*)&part[8192 + rloc1 * 64 + cc];
            float o0 = (oacc[nb2][0] + a0.x + b0.x + c0.x) * i0;
            float o1 = (oacc[nb2][1] + a0.y + b0.y + c0.y) * i0;
            float o2 = (oacc[nb2][2] + a1.x + b1.x + c1.x) * i1;
            float o3 = (oacc[nb2][3] + a1.y + b1.y + c1.y) * i1;
            int col = h * KS_ + cc;
            size_t d0 = ((size_t)b * S_ + q0 + rloc0) * D_ + col;
            size_t d1 = ((size_t)b * S_ + q0 + rloc1) * D_ + col;
            u32 h0 = f2bf_bits(o0), h1 = f2bf_bits(o1);
            u32 h2 = f2bf_bits(o2), h3 = f2bf_bits(o3);
            u32 l0 = f2bf_bits(o0 - __uint_as_float(h0 << 16));
            u32 l1 = f2bf_bits(o1 - __uint_as_float(h1 << 16));
            u32 l2 = f2bf_bits(o2 - __uint_as_float(h2 << 16));
            u32 l3 = f2bf_bits(o3 - __uint_as_float(h3 << 16));
            *(u32*)&CtxH[d0] = h0 | (h1 << 16);
            *(u32*)&CtxL[d0] = l0 | (l1 << 16);
            *(u32*)&CtxH[d1] = h2 | (h3 << 16);
            *(u32*)&CtxL[d1] = l2 | (l3 << 16);
        }
    }
}

// Normalize align: factor = exp(m_used - m_final) / sum. One block per row.
__global__ void __launch_bounds__(256) fixup(
    float* __restrict__ align, const float* __restrict__ mu,
    const float* __restrict__ mfin, const float* __restrict__ isv) {
    size_t R = blockIdx.x;
    float mf = mfin[R];
    float is = isv[R];
    const float* m = mu + R * NCH;
    float* row = align + R * S_;
    __shared__ float fac[NCH];
    if (threadIdx.x < NCH) fac[threadIdx.x] = exp_fast(m[threadIdx.x] - mf) * is;
    __syncthreads();
    for (int i = threadIdx.x * 4; i < S_; i += 256 * 4) {
        float f = fac[i >> 7];
        float4 v = *(float4*)&row[i];
        v.x *= f; v.y *= f; v.z *= f; v.w *= f;
        *(float4*)&row[i] = v;
    }
}

// ---------------------------------------------------------------------------
extern "C" void kernel_launch(void* const* d_in, const int* in_sizes, int n_in,
                              void* d_out, int out_size) {
    const float* q    = (const float*)d_in[0];
    const float* v    = (const float*)d_in[1];
    const float* mask = (const float*)d_in[2];
    const float* wq_w = (const float*)d_in[3];
    const float* wq_b = (const float*)d_in[4];
    const float* wk_w = (const float*)d_in[5];
    const float* wk_b = (const float*)d_in[6];
    const float* wv_w = (const float*)d_in[7];
    const float* wv_b = (const float*)d_in[8];
    const float* wo_w = (const float*)d_in[9];
    const float* wo_b = (const float*)d_in[10];

    float* out = (float*)d_out;
    float* heads = out;
    float* align = out + NTOK;

    float* scratch = nullptr;
    cudaGetSymbolAddress((void**)&scratch, g_scratch);

    __nv_bfloat16* AqH = (__nv_bfloat16*)(scratch + 0 * F_ACT);
    __nv_bfloat16* AqL = (__nv_bfloat16*)(scratch + 1 * F_ACT);
    __nv_bfloat16* AvH = (__nv_bfloat16*)(scratch + 2 * F_ACT);
    __nv_bfloat16* AvL = (__nv_bfloat16*)(scratch + 3 * F_ACT);
    __nv_bfloat16* QsH = (__nv_bfloat16*)(scratch + 4 * F_ACT);
    __nv_bfloat16* QsL = (__nv_bfloat16*)(scratch + 5 * F_ACT);
    __nv_bfloat16* KsH = (__nv_bfloat16*)(scratch + 6 * F_ACT);
    __nv_bfloat16* KsL = (__nv_bfloat16*)(scratch + 7 * F_ACT);
    __nv_bfloat16* VsH = (__nv_bfloat16*)(scratch + 8 * F_ACT);
    __nv_bfloat16* VsL = (__nv_bfloat16*)(scratch + 9 * F_ACT);
    float* wb = scratch + 10 * F_ACT;
    __nv_bfloat16* WqH = (__nv_bfloat16*)(wb + 0 * F_W);
    __nv_bfloat16* WqL = (__nv_bfloat16*)(wb + 1 * F_W);
    __nv_bfloat16* WkH = (__nv_bfloat16*)(wb + 2 * F_W);
    __nv_bfloat16* WkL = (__nv_bfloat16*)(wb + 3 * F_W);
    __nv_bfloat16* WvH = (__nv_bfloat16*)(wb + 4 * F_W);
    __nv_bfloat16* WvL = (__nv_bfloat16*)(wb + 5 * F_W);
    __nv_bfloat16* WoH = (__nv_bfloat16*)(wb + 6 * F_W);
    __nv_bfloat16* WoL = (__nv_bfloat16*)(wb + 7 * F_W);

    // softmax stats scratch (reuses AvH slot — AvH/AvL are dead after gemm_split)
    float* mu_s  = scratch + 2 * F_ACT;                    // 32*2048*16 floats = 1M
    float* mf_s  = mu_s + (size_t)B_ * H_ * S_ * NCH;      // 64K floats
    float* is_s  = mf_s + (size_t)B_ * H_ * S_;            // 64K floats

    cudaFuncSetAttribute(gemm_mma, cudaFuncAttributeMaxDynamicSharedMemorySize, GSMEM);
    cudaFuncSetAttribute(gemm_split, cudaFuncAttributeMaxDynamicSharedMemorySize, GSMEM);
    cudaFuncSetAttribute(flash_attn, cudaFuncAttributeMaxDynamicSharedMemorySize, FL_SMEM);

    int nAct = (int)NTOK;
    int gA = (nAct / 4 + 255) / 256;

    conv_w4<<<dim3(32, 32, 4), dim3(32, 8)>>>(wq_w, wk_w, wv_w, wo_w,
                                              WqH, WqL, WkH, WkL,
                                              WvH, WvL, WoH, WoL);
    conv_act<<<gA, 256>>>(q, AqH, AqL, nAct);
    conv_act<<<gA, 256>>>(v, AvH, AvL, nAct);

    dim3 gproj(D_ / 128, (B_ * S_) / 128);
    gemm_split<<<gproj, 256, GSMEM>>>(AqH, AqL, WqH, WqL, wq_b, QsH, QsL);
    gemm_split<<<gproj, 256, GSMEM>>>(AvH, AvL, WkH, WkL, wk_b, KsH, KsL);
    gemm_split<<<gproj, 256, GSMEM>>>(AvH, AvL, WvH, WvL, wv_b, VsH, VsL);

    dim3 gfa(S_ / QT, B_ * H_);                   // (32, 32)
    flash_attn<<<gfa, FT, FL_SMEM>>>(QsH, QsL, KsH, KsL, VsH, VsL,
                                     mask, align, mu_s, mf_s, is_s, AqH, AqL);

    fixup<<<B_ * H_ * S_, 256>>>(align, mu_s, mf_s, is_s);

    gemm_mma<<<gproj, 256, GSMEM>>>(AqH, AqL, WoH, WoL, wo_b, heads);
}

// round 12
// speedup vs baseline: 2.1949x; 1.0416x over previous
#include <cuda_runtime.h>
#include <cuda_bf16.h>
#include <cstdint>

#define B_  2
#define S_  2048
#define D_  1024
#define H_  16
#define KS_ 64
#define NEG_BIG (-1.0e9f)

#define NTOK ((size_t)B_ * S_ * D_)

#define F_ACT   (NTOK / 2)            // float slots per bf16 [B,S,D] array
#define F_W     ((size_t)D_ * D_ / 2)
__device__ __align__(16) float g_scratch[10 * F_ACT + 8 * F_W];

typedef uint32_t u32;

// ============================ helpers ======================================
__device__ __forceinline__ u32 smem_u32(const void* p) {
    u32 a;
    asm("{ .reg .u64 t; cvta.to.shared.u64 t, %1; cvt.u32.u64 %0, t; }"
        : "=r"(a) : "l"(p));
    return a;
}
__device__ __forceinline__ void cp_async16(u32 saddr, const void* gaddr) {
    asm volatile("cp.async.cg.shared.global [%0], [%1], 16;"
                 :: "r"(saddr), "l"(gaddr) : "memory");
}
__device__ __forceinline__ void cp_commit() {
    asm volatile("cp.async.commit_group;" ::: "memory");
}
template <int N>
__device__ __forceinline__ void cp_wait() {
    asm volatile("cp.async.wait_group %0;" :: "n"(N) : "memory");
}
__device__ __forceinline__ void mma16816(float* d, u32 a0, u32 a1,
                                         u32 a2, u32 a3, u32 b0, u32 b1) {
    asm volatile(
        "mma.sync.aligned.m16n8k16.row.col.f32.bf16.bf16.f32 "
        "{%0,%1,%2,%3}, {%4,%5,%6,%7}, {%8,%9}, {%0,%1,%2,%3};"
        : "+f"(d[0]), "+f"(d[1]), "+f"(d[2]), "+f"(d[3])
        : "r"(a0), "r"(a1), "r"(a2), "r"(a3), "r"(b0), "r"(b1));
}
__device__ __forceinline__ void ldsm_x2_t(u32& r0, u32& r1, u32 a) {
    asm volatile("ldmatrix.sync.aligned.m8n8.x2.trans.shared.b16 {%0,%1}, [%2];"
                 : "=r"(r0), "=r"(r1) : "r"(a));
}
__device__ __forceinline__ u32 f2bf_bits(float x) {
    u32 u = __float_as_uint(x);
    return (u + 0x7FFFu + ((u >> 16) & 1u)) >> 16;
}
__device__ __forceinline__ float exp_fast(float x) {
    x = fmaxf(x, -87.3f);
    float y = x * 1.44269504089f;
    float n = rintf(y);
    float f = y - n;
    float p = 1.33336498402e-3f;
    p = fmaf(p, f, 9.61793571616e-3f);
    p = fmaf(p, f, 5.55043442248e-2f);
    p = fmaf(p, f, 2.40226506959e-1f);
    p = fmaf(p, f, 6.93147180560e-1f);
    p = fmaf(p, f, 1.0f);
    return __int_as_float(__float_as_int(p) + (((int)n) << 23));
}

// ======================= conversion kernels ================================
// both activations in one launch: z selects (x, h, l)
__global__ void conv_act2(const float* __restrict__ x0, __nv_bfloat16* __restrict__ h0,
                          __nv_bfloat16* __restrict__ l0,
                          const float* __restrict__ x1, __nv_bfloat16* __restrict__ h1,
                          __nv_bfloat16* __restrict__ l1, int n) {
    const float* x = blockIdx.z ? x1 : x0;
    __nv_bfloat16* h = blockIdx.z ? h1 : h0;
    __nv_bfloat16* l = blockIdx.z ? l1 : l0;
    int i = blockIdx.x * blockDim.x + threadIdx.x;
    int i4 = i * 4;
    if (i4 >= n) return;
    float4 v = *(const float4*)(x + i4);
    float vs[4] = {v.x, v.y, v.z, v.w};
    __nv_bfloat16 hh[4], ll[4];
    #pragma unroll
    for (int j = 0; j < 4; j++) {
        __nv_bfloat16 hi = __float2bfloat16_rn(vs[j]);
        float r = vs[j] - __bfloat162float(hi);
        hh[j] = hi;
        ll[j] = __float2bfloat16_rn(r);
    }
    __nv_bfloat162* H2 = (__nv_bfloat162*)(h + i4);
    __nv_bfloat162* L2 = (__nv_bfloat162*)(l + i4);
    H2[0] = __nv_bfloat162(hh[0], hh[1]);
    H2[1] = __nv_bfloat162(hh[2], hh[3]);
    L2[0] = __nv_bfloat162(ll[0], ll[1]);
    L2[1] = __nv_bfloat162(ll[2], ll[3]);
}

__global__ void conv_w4(const float* __restrict__ W0, const float* __restrict__ W1,
                        const float* __restrict__ W2, const float* __restrict__ W3,
                        __nv_bfloat16* __restrict__ T0h, __nv_bfloat16* __restrict__ T0l,
                        __nv_bfloat16* __restrict__ T1h, __nv_bfloat16* __restrict__ T1l,
                        __nv_bfloat16* __restrict__ T2h, __nv_bfloat16* __restrict__ T2l,
                        __nv_bfloat16* __restrict__ T3h, __nv_bfloat16* __restrict__ T3l) {
    __shared__ float t[32][33];
    const float* W;
    __nv_bfloat16 *Th, *Tl;
    switch (blockIdx.z) {
        case 0: W = W0; Th = T0h; Tl = T0l; break;
        case 1: W = W1; Th = T1h; Tl = T1l; break;
        case 2: W = W2; Th = T2h; Tl = T2l; break;
        default: W = W3; Th = T3h; Tl = T3l; break;
    }
    int n0 = blockIdx.x * 32, k0 = blockIdx.y * 32;
    int tx = threadIdx.x, ty = threadIdx.y;
    for (int r = ty; r < 32; r += 8)
        t[r][tx] = W[(size_t)(k0 + r) * D_ + n0 + tx];
    __syncthreads();
    for (int r = ty; r < 32; r += 8) {
        float x = t[tx][r];
        __nv_bfloat16 hi = __float2bfloat16_rn(x);
        float res = x - __bfloat162float(hi);
        size_t o = (size_t)(n0 + r) * D_ + k0 + tx;
        Th[o] = hi;
        Tl[o] = __float2bfloat16_rn(res);
    }
}

// ======================= HMMA GEMM core (R5-verified) ======================
#define GROW   80
#define GTILE  (128 * GROW)
#define GSTAGE (4 * GTILE)
#define GSMEM  (2 * GSTAGE)

#define GEMM_BODY(ACC)                                                          \
    const u32 sb = smem_u32(smem);                                              \
    const int tid  = threadIdx.x;                                               \
    const int lane = tid & 31;                                                  \
    const int wid  = tid >> 5;                                                  \
    const int wm   = wid >> 2;                                                  \
    const int wn   = wid & 3;                                                   \
    const int g    = lane >> 2;                                                 \
    const int q    = lane & 3;                                                  \
    const int n0 = blockIdx.x * 128;                                            \
    const int m0 = blockIdx.y * 128;                                            \
    const int cid0 = tid * 2;                                                   \
    const int row0 = cid0 >> 2;                                                 \
    const int cc0  = (cid0 & 3) * 8;                                            \
    const int row1 = (cid0 + 1) >> 2;                                           \
    const int cc1  = ((cid0 + 1) & 3) * 8;                                      \
    const int NK = D_ / 32;                                                     \
    {                                                                           \
        u32 s = sb;                                                             \
        cp_async16(s + 0 * GTILE + row0 * GROW + (cc0 & 31) * 2, Ah + (size_t)(m0 + row0) * D_ + cc0); \
        cp_async16(s + 0 * GTILE + row1 * GROW + (cc1 & 31) * 2, Ah + (size_t)(m0 + row1) * D_ + cc1); \
        cp_async16(s + 1 * GTILE + row0 * GROW + (cc0 & 31) * 2, Al + (size_t)(m0 + row0) * D_ + cc0); \
        cp_async16(s + 1 * GTILE + row1 * GROW + (cc1 & 31) * 2, Al + (size_t)(m0 + row1) * D_ + cc1); \
        cp_async16(s + 2 * GTILE + row0 * GROW + (cc0 & 31) * 2, Bh + (size_t)(n0 + row0) * D_ + cc0); \
        cp_async16(s + 2 * GTILE + row1 * GROW + (cc1 & 31) * 2, Bh + (size_t)(n0 + row1) * D_ + cc1); \
        cp_async16(s + 3 * GTILE + row0 * GROW + (cc0 & 31) * 2, Bl + (size_t)(n0 + row0) * D_ + cc0); \
        cp_async16(s + 3 * GTILE + row1 * GROW + (cc1 & 31) * 2, Bl + (size_t)(n0 + row1) * D_ + cc1); \
        cp_commit();                                                            \
    }                                                                           \
    for (int ks = 0; ks < NK; ks++) {                                           \
        if (ks + 1 < NK) {                                                      \
            int k0 = (ks + 1) * 32;                                             \
            u32 s = sb + ((ks + 1) & 1) * GSTAGE;                               \
            cp_async16(s + 0 * GTILE + row0 * GROW + (cc0 & 31) * 2, Ah + (size_t)(m0 + row0) * D_ + k0 + cc0); \
            cp_async16(s + 0 * GTILE + row1 * GROW + (cc1 & 31) * 2, Ah + (size_t)(m0 + row1) * D_ + k0 + cc1); \
            cp_async16(s + 1 * GTILE + row0 * GROW + (cc0 & 31) * 2, Al + (size_t)(m0 + row0) * D_ + k0 + cc0); \
            cp_async16(s + 1 * GTILE + row1 * GROW + (cc1 & 31) * 2, Al + (size_t)(m0 + row1) * D_ + k0 + cc1); \
            cp_async16(s + 2 * GTILE + row0 * GROW + (cc0 & 31) * 2, Bh + (size_t)(n0 + row0) * D_ + k0 + cc0); \
            cp_async16(s + 2 * GTILE + row1 * GROW + (cc1 & 31) * 2, Bh + (size_t)(n0 + row1) * D_ + k0 + cc1); \
            cp_async16(s + 3 * GTILE + row0 * GROW + (cc0 & 31) * 2, Bl + (size_t)(n0 + row0) * D_ + k0 + cc0); \
            cp_async16(s + 3 * GTILE + row1 * GROW + (cc1 & 31) * 2, Bl + (size_t)(n0 + row1) * D_ + k0 + cc1); \
            cp_commit();                                                        \
            cp_wait<1>();                                                       \
        } else {                                                                \
            cp_wait<0>();                                                       \
        }                                                                       \
        __syncthreads();                                                        \
        const char* st  = smem + (ks & 1) * GSTAGE;                             \
        const char* sAh = st;                                                   \
        const char* sAl = st + GTILE;                                           \
        const char* sBh = st + 2 * GTILE;                                       \
        const char* sBl = st + 3 * GTILE;                                       \
        _Pragma("unroll")                                                       \
        for (int kk = 0; kk < 32; kk += 16) {                                   \
            u32 bh[4][2], bl[4][2];                                             \
            _Pragma("unroll")                                                   \
            for (int j = 0; j < 4; j++) {                                       \
                int n = wn * 32 + j * 8 + g;                                    \
                int o0 = n * GROW + (kk + 2 * q) * 2;                           \
                int o1 = n * GROW + (kk + 2 * q + 8) * 2;                       \
                bh[j][0] = *(const u32*)(sBh + o0);                             \
                bh[j][1] = *(const u32*)(sBh + o1);                             \
                bl[j][0] = *(const u32*)(sBl + o0);                             \
                bl[j][1] = *(const u32*)(sBl + o1);                             \
            }                                                                   \
            _Pragma("unroll")                                                   \
            for (int i = 0; i < 4; i++) {                                       \
                int m = wm * 64 + i * 16;                                       \
                int r0 = (m + g) * GROW;                                        \
                int r1 = (m + g + 8) * GROW;                                    \
                int c0 = (kk + 2 * q) * 2;                                      \
                int c1 = (kk + 2 * q + 8) * 2;                                  \
                u32 ah0 = *(const u32*)(sAh + r0 + c0);                         \
                u32 ah1 = *(const u32*)(sAh + r1 + c0);                         \
                u32 ah2 = *(const u32*)(sAh + r0 + c1);                         \
                u32 ah3 = *(const u32*)(sAh + r1 + c1);                         \
                u32 al0 = *(const u32*)(sAl + r0 + c0);                         \
                u32 al1 = *(const u32*)(sAl + r1 + c0);                         \
                u32 al2 = *(const u32*)(sAl + r0 + c1);                         \
                u32 al3 = *(const u32*)(sAl + r1 + c1);                         \
                _Pragma("unroll")                                               \
                for (int j = 0; j < 4; j++) {                                   \
                    mma16816(ACC[i][j], ah0, ah1, ah2, ah3, bh[j][0], bh[j][1]);\
                    mma16816(ACC[i][j], ah0, ah1, ah2, ah3, bl[j][0], bl[j][1]);\
                    mma16816(ACC[i][j], al0, al1, al2, al3, bh[j][0], bh[j][1]);\
                }                                                               \
            }                                                                   \
        }                                                                       \
        __syncthreads();                                                        \
    }

__global__ void __launch_bounds__(256) gemm_mma(
    const __nv_bfloat16* __restrict__ Ah, const __nv_bfloat16* __restrict__ Al,
    const __nv_bfloat16* __restrict__ Bh, const __nv_bfloat16* __restrict__ Bl,
    const float* __restrict__ bias, float* __restrict__ C) {
    extern __shared__ char smem[];
    float acc[4][4][4] = {};
    GEMM_BODY(acc)
    #pragma unroll
    for (int i = 0; i < 4; i++) {
        int row = m0 + wm * 64 + i * 16;
        #pragma unroll
        for (int j = 0; j < 4; j++) {
            int col = n0 + wn * 32 + j * 8 + 2 * q;
            float b0 = __ldg(bias + col);
            float b1 = __ldg(bias + col + 1);
            float2 v0 = make_float2(acc[i][j][0] + b0, acc[i][j][1] + b1);
            float2 v1 = make_float2(acc[i][j][2] + b0, acc[i][j][3] + b1);
            *(float2*)&C[(size_t)(row + g) * D_ + col]     = v0;
            *(float2*)&C[(size_t)(row + g + 8) * D_ + col] = v1;
        }
    }
}

// Q/K/V projections in ONE launch: grid.z selects (A, W, bias, out) set.
__global__ void __launch_bounds__(256) gemm_split3(
    const __nv_bfloat16* __restrict__ Aq_h, const __nv_bfloat16* __restrict__ Aq_l,
    const __nv_bfloat16* __restrict__ Av_h, const __nv_bfloat16* __restrict__ Av_l,
    const __nv_bfloat16* __restrict__ Wq_h, const __nv_bfloat16* __restrict__ Wq_l,
    const __nv_bfloat16* __restrict__ Wk_h, const __nv_bfloat16* __restrict__ Wk_l,
    const __nv_bfloat16* __restrict__ Wv_h, const __nv_bfloat16* __restrict__ Wv_l,
    const float* __restrict__ bq, const float* __restrict__ bk, const float* __restrict__ bv,
    __nv_bfloat16* __restrict__ Q_h, __nv_bfloat16* __restrict__ Q_l,
    __nv_bfloat16* __restrict__ K_h, __nv_bfloat16* __restrict__ K_l,
    __nv_bfloat16* __restrict__ V_h, __nv_bfloat16* __restrict__ V_l) {
    extern __shared__ char smem[];
    const __nv_bfloat16 *Ah, *Al, *Bh, *Bl;
    const float* bias;
    __nv_bfloat16 *Ch, *Cl;
    switch (blockIdx.z) {
        case 0:  Ah = Aq_h; Al = Aq_l; Bh = Wq_h; Bl = Wq_l; bias = bq; Ch = Q_h; Cl = Q_l; break;
        case 1:  Ah = Av_h; Al = Av_l; Bh = Wk_h; Bl = Wk_l; bias = bk; Ch = K_h; Cl = K_l; break;
        default: Ah = Av_h; Al = Av_l; Bh = Wv_h; Bl = Wv_l; bias = bv; Ch = V_h; Cl = V_l; break;
    }
    float acc[4][4][4] = {};
    GEMM_BODY(acc)
    #pragma unroll
    for (int i = 0; i < 4; i++) {
        int row = m0 + wm * 64 + i * 16;
        #pragma unroll
        for (int j = 0; j < 4; j++) {
            int col = n0 + wn * 32 + j * 8 + 2 * q;
            float b0 = __ldg(bias + col);
            float b1 = __ldg(bias + col + 1);
            float vs[4] = {acc[i][j][0] + b0, acc[i][j][1] + b1,
                           acc[i][j][2] + b0, acc[i][j][3] + b1};
            u32 hb[4], lb[4];
            #pragma unroll
            for (int t = 0; t < 4; t++) {
                hb[t] = f2bf_bits(vs[t]);
                lb[t] = f2bf_bits(vs[t] - __uint_as_float(hb[t] << 16));
            }
            size_t o0 = (size_t)(row + g) * D_ + col;
            size_t o1 = (size_t)(row + g + 8) * D_ + col;
            *(u32*)&Ch[o0] = hb[0] | (hb[1] << 16);
            *(u32*)&Cl[o0] = lb[0] | (lb[1] << 16);
            *(u32*)&Ch[o1] = hb[2] | (hb[3] << 16);
            *(u32*)&Cl[o1] = lb[2] | (lb[3] << 16);
        }
    }
}

// ======================= flash attention (512 thr, QT=128) =================
// Block = 128 q-rows x one (b,h). 16 warps: wr=w>>1 (row group), wc=w&1 (k half).
// Online softmax, unnormalized align + fixup (as R11). P/V interleaved per
// 16-k slice to bound register pressure.
#define QT 128
#define NCH 16
#define KROW 144
#define CTILE (128 * KROW)                 // 18432
#define CSTG  (2 * CTILE)                  // 36864
#define KB_OFF 0
#define VB_OFF (2 * CSTG)                  // 73728
#define QB_OFF (4 * CSTG)                  // 147456 (Q: 2 planes x 128 x 144)
#define ST_OFF (QB_OFF + 2 * QT * KROW)    // 184320
#define FL_SMEM (ST_OFF + 4608)            // 188928
#define FT 512

__device__ __forceinline__ void fl_stage(u32 dst, const __nv_bfloat16* Xh,
                                         const __nv_bfloat16* Xl,
                                         int b, int h, int c, int tid) {
    #pragma unroll
    for (int i = tid; i < 2048; i += FT) {
        int which = i >> 10, j = i & 1023, row = j >> 3, sub = j & 7;
        const __nv_bfloat16* src = (which ? Xl : Xh) +
            ((size_t)b * S_ + (size_t)c * 128 + row) * D_ + h * KS_ + sub * 8;
        cp_async16(dst + which * CTILE + row * KROW + sub * 16, src);
    }
}

__global__ void __launch_bounds__(FT, 1) flash_attn(
    const __nv_bfloat16* __restrict__ Qh, const __nv_bfloat16* __restrict__ Ql,
    const __nv_bfloat16* __restrict__ Kh, const __nv_bfloat16* __restrict__ Kl,
    const __nv_bfloat16* __restrict__ Vh, const __nv_bfloat16* __restrict__ Vl,
    const float* __restrict__ mask, float* __restrict__ align,
    float* __restrict__ mu, float* __restrict__ mfin, float* __restrict__ isv,
    __nv_bfloat16* __restrict__ CtxH, __nv_bfloat16* __restrict__ CtxL) {
    extern __shared__ char smem[];
    const u32 sb = smem_u32(smem);

    const int tid = threadIdx.x, lane = tid & 31, w = tid >> 5;
    const int g = lane >> 2, qq = lane & 3;
    const int wr = w >> 1, wc = w & 1;            // 8 row-groups x 2 k-halves
    const int bh = blockIdx.y, b = bh >> 4, h = bh & 15;
    const int q0 = blockIdx.x * QT;

    fl_stage(sb + QB_OFF, Qh, Ql, b, h, blockIdx.x, tid);   // Q (128 rows)
    fl_stage(sb + KB_OFF, Kh, Kl, b, h, 0, tid);
    fl_stage(sb + VB_OFF, Vh, Vl, b, h, 0, tid);
    cp_commit();

    float* m_state = (float*)(smem + ST_OFF);     // [128]
    float* s_state = m_state + 128;               // [128]
    float* scalef  = s_state + 128;               // [128]
    float* pmax    = scalef + 128;                // [2][128]
    float* psum    = pmax + 256;                  // [2][128]
    if (tid < 128) { m_state[tid] = -3.0e38f; s_state[tid] = 0.0f; }

    u32 ahq[4][4], alq[4][4];
    float oacc[8][4] = {};
    const float* mrow = mask + (size_t)b * S_ * S_;
    const int rloc0 = wr * 16 + g;
    const int rloc1 = rloc0 + 8;

    for (int c = 0; c < NCH; c++) {
        if (c + 1 < NCH) {
            u32 boff = ((c + 1) & 1) * CSTG;
            fl_stage(sb + KB_OFF + boff, Kh, Kl, b, h, c + 1, tid);
            fl_stage(sb + VB_OFF + boff, Vh, Vl, b, h, c + 1, tid);
            cp_commit();
            cp_wait<1>();
        } else {
            cp_wait<0>();
        }
        __syncthreads();                           // S1

        if (c == 0) {
            const char* sQh = smem + QB_OFF;
            const char* sQl = sQh + QT * KROW;
            #pragma unroll
            for (int ks = 0; ks < 4; ks++) {
                int r0 = rloc0 * KROW, r1 = rloc1 * KROW;
                int c0 = (ks * 16 + 2 * qq) * 2, c1 = c0 + 16;
                ahq[ks][0] = *(const u32*)(sQh + r0 + c0);
                ahq[ks][1] = *(const u32*)(sQh + r1 + c0);
                ahq[ks][2] = *(const u32*)(sQh + r0 + c1);
                ahq[ks][3] = *(const u32*)(sQh + r1 + c1);
                alq[ks][0] = *(const u32*)(sQl + r0 + c0);
                alq[ks][1] = *(const u32*)(sQl + r1 + c0);
                alq[ks][2] = *(const u32*)(sQl + r0 + c1);
                alq[ks][3] = *(const u32*)(sQl + r1 + c1);
            }
        }

        // ---- scores: warp covers 16q x 64k (8 n-blocks of 8) ----
        const char* sKh = smem + KB_OFF + (c & 1) * CSTG;
        const char* sKl = sKh + CTILE;
        float sacc[8][4] = {};
        #pragma unroll
        for (int ks = 0; ks < 4; ks++) {
            #pragma unroll
            for (int nb = 0; nb < 8; nb++) {
                int krow = (wc * 64 + nb * 8 + g) * KROW;
                int ko = (ks * 16 + 2 * qq) * 2;
                u32 b0 = *(const u32*)(sKh + krow + ko);
                u32 b1 = *(const u32*)(sKh + krow + ko + 16);
                u32 l0 = *(const u32*)(sKl + krow + ko);
                u32 l1 = *(const u32*)(sKl + krow + ko + 16);
                mma16816(sacc[nb], ahq[ks][0], ahq[ks][1], ahq[ks][2], ahq[ks][3], b0, b1);
                mma16816(sacc[nb], ahq[ks][0], ahq[ks][1], ahq[ks][2], ahq[ks][3], l0, l1);
                mma16816(sacc[nb], alq[ks][0], alq[ks][1], alq[ks][2], alq[ks][3], b0, b1);
            }
        }

        // ---- mask + scale + chunk max ----
        float mx0 = -3.0e38f, mx1 = -3.0e38f;
        #pragma unroll
        for (int nb = 0; nb < 8; nb++) {
            int col = c * 128 + wc * 64 + nb * 8 + 2 * qq;
            float2 m0 = *(const float2*)&mrow[(size_t)(q0 + rloc0) * S_ + col];
            float2 m1 = *(const float2*)&mrow[(size_t)(q0 + rloc1) * S_ + col];
            float s0 = sacc[nb][0] * 0.125f * m0.x; if (s0 == 0.0f) s0 = NEG_BIG;
            float s1 = sacc[nb][1] * 0.125f * m0.y; if (s1 == 0.0f) s1 = NEG_BIG;
            float s2 = sacc[nb][2] * 0.125f * m1.x; if (s2 == 0.0f) s2 = NEG_BIG;
            float s3 = sacc[nb][3] * 0.125f * m1.y; if (s3 == 0.0f) s3 = NEG_BIG;
            sacc[nb][0] = s0; sacc[nb][1] = s1; sacc[nb][2] = s2; sacc[nb][3] = s3;
            mx0 = fmaxf(mx0, fmaxf(s0, s1));
            mx1 = fmaxf(mx1, fmaxf(s2, s3));
        }
        mx0 = fmaxf(mx0, __shfl_xor_sync(0xffffffffu, mx0, 1));
        mx0 = fmaxf(mx0, __shfl_xor_sync(0xffffffffu, mx0, 2));
        mx1 = fmaxf(mx1, __shfl_xor_sync(0xffffffffu, mx1, 1));
        mx1 = fmaxf(mx1, __shfl_xor_sync(0xffffffffu, mx1, 2));
        if (qq == 0) {
            pmax[wc * 128 + rloc0] = mx0;
            pmax[wc * 128 + rloc1] = mx1;
        }
        __syncthreads();                           // S2

        if (tid < 128) {
            float mch = fmaxf(pmax[tid], pmax[128 + tid]);
            float mold = m_state[tid];
            float mnew = fmaxf(mold, mch);
            float f = exp_fast(mold - mnew);
            scalef[tid] = f;
            m_state[tid] = mnew;
            s_state[tid] *= f;
            mu[((size_t)bh * S_ + q0 + tid) * NCH + c] = mnew;
        }
        __syncthreads();                           // S3

        // ---- O rescale; probs/align/PV interleaved per 16-k slice ----
        float mn0 = m_state[rloc0], mn1 = m_state[rloc1];
        float f0 = scalef[rloc0], f1 = scalef[rloc1];
        #pragma unroll
        for (int nb2 = 0; nb2 < 8; nb2++) {
            oacc[nb2][0] *= f0; oacc[nb2][1] *= f0;
            oacc[nb2][2] *= f1; oacc[nb2][3] *= f1;
        }
        float ps0 = 0.f, ps1 = 0.f;
        u32 vb = sb + VB_OFF + (c & 1) * CSTG;
        #pragma unroll
        for (int kf = 0; kf < 4; kf++) {
            u32 pah[4], pal[4];
            #pragma unroll
            for (int half = 0; half < 2; half++) {
                int nb = kf * 2 + half;
                float p0 = exp_fast(sacc[nb][0] - mn0);
                float p1 = exp_fast(sacc[nb][1] - mn0);
                float p2 = exp_fast(sacc[nb][2] - mn1);
                float p3 = exp_fast(sacc[nb][3] - mn1);
                ps0 += p0 + p1; ps1 += p2 + p3;
                int col = c * 128 + wc * 64 + nb * 8 + 2 * qq;
                *(float2*)&align[((size_t)bh * S_ + q0 + rloc0) * S_ + col] = make_float2(p0, p1);
                *(float2*)&align[((size_t)bh * S_ + q0 + rloc1) * S_ + col] = make_float2(p2, p3);
                u32 hb0 = f2bf_bits(p0), hb1 = f2bf_bits(p1);
                u32 hb2 = f2bf_bits(p2), hb3 = f2bf_bits(p3);
                u32 lb0 = f2bf_bits(p0 - __uint_as_float(hb0 << 16));
                u32 lb1 = f2bf_bits(p1 - __uint_as_float(hb1 << 16));
                u32 lb2 = f2bf_bits(p2 - __uint_as_float(hb2 << 16));
                u32 lb3 = f2bf_bits(p3 - __uint_as_float(hb3 << 16));
                int sl = half * 2;
                pah[sl + 0] = hb0 | (hb1 << 16);
                pah[sl + 1] = hb2 | (hb3 << 16);
                pal[sl + 0] = lb0 | (lb1 << 16);
                pal[sl + 1] = lb2 | (lb3 << 16);
            }
            u32 vaddr = vb + (wc * 64 + kf * 16 + (lane & 15)) * KROW;
            #pragma unroll
            for (int nb2 = 0; nb2 < 8; nb2++) {
                u32 vh0, vh1, vl0, vl1;
                ldsm_x2_t(vh0, vh1, vaddr + nb2 * 16);
                ldsm_x2_t(vl0, vl1, vaddr + nb2 * 16 + CTILE);
                mma16816(oacc[nb2], pah[0], pah[1], pah[2], pah[3], vh0, vh1);
                mma16816(oacc[nb2], pah[0], pah[1], pah[2], pah[3], vl0, vl1);
                mma16816(oacc[nb2], pal[0], pal[1], pal[2], pal[3], vh0, vh1);
            }
        }
        ps0 += __shfl_xor_sync(0xffffffffu, ps0, 1);
        ps0 += __shfl_xor_sync(0xffffffffu, ps0, 2);
        ps1 += __shfl_xor_sync(0xffffffffu, ps1, 1);
        ps1 += __shfl_xor_sync(0xffffffffu, ps1, 2);
        if (qq == 0) {
            psum[wc * 128 + rloc0] = ps0;
            psum[wc * 128 + rloc1] = ps1;
        }
        __syncthreads();                           // S4
        if (tid < 128)
            s_state[tid] += psum[tid] + psum[128 + tid];
    }

    // ---- finalize stats ----
    if (tid < 128) {
        size_t R = (size_t)bh * S_ + q0 + tid;
        float inv = 1.0f / s_state[tid];
        mfin[R] = m_state[tid];
        isv[R] = inv;
        scalef[tid] = inv;
    }
    __syncthreads();

    // ---- reduce O across 2 k-halves (reuse K/V smem) ----
    float* part = (float*)smem;                    // 128 x 64 floats = 32 KB
    if (wc == 1) {
        #pragma unroll
        for (int nb2 = 0; nb2 < 8; nb2++) {
            int cc = nb2 * 8 + 2 * qq;
            *(float2*)&part[rloc0 * 64 + cc] = make_float2(oacc[nb2][0], oacc[nb2][1]);
            *(float2*)&part[rloc1 * 64 + cc] = make_float2(oacc[nb2][2], oacc[nb2][3]);
        }
    }
    __syncthreads();
    if (wc == 0) {
        float i0 = scalef[rloc0], i1 = scalef[rloc1];
        #pragma unroll
        for (int nb2 = 0; nb2 < 8; nb2++) {
            int cc = nb2 * 8 + 2 * qq;
            float2 a0 = *(const float2*)&part[rloc0 * 64 + cc];
            float2 a1 = *(const float2*)&part[rloc1 * 64 + cc];
            float o0 = (oacc[nb2][0] + a0.x) * i0;
            float o1 = (oacc[nb2][1] + a0.y) * i0;
            float o2 = (oacc[nb2][2] + a1.x) * i1;
            float o3 = (oacc[nb2][3] + a1.y) * i1;
            int col = h * KS_ + cc;
            size_t d0 = ((size_t)b * S_ + q0 + rloc0) * D_ + col;
            size_t d1 = ((size_t)b * S_ + q0 + rloc1) * D_ + col;
            u32 h0 = f2bf_bits(o0), h1 = f2bf_bits(o1);
            u32 h2 = f2bf_bits(o2), h3 = f2bf_bits(o3);
            u32 l0 = f2bf_bits(o0 - __uint_as_float(h0 << 16));
            u32 l1 = f2bf_bits(o1 - __uint_as_float(h1 << 16));
            u32 l2 = f2bf_bits(o2 - __uint_as_float(h2 << 16));
            u32 l3 = f2bf_bits(o3 - __uint_as_float(h3 << 16));
            *(u32*)&CtxH[d0] = h0 | (h1 << 16);
            *(u32*)&CtxL[d0] = l0 | (l1 << 16);
            *(u32*)&CtxH[d1] = h2 | (h3 << 16);
            *(u32*)&CtxL[d1] = l2 | (l3 << 16);
        }
    }
}

// Normalize align: factor = exp(m_used - m_final) / sum. One block per row.
__global__ void __launch_bounds__(256) fixup(
    float* __restrict__ align, const float* __restrict__ mu,
    const float* __restrict__ mfin, const float* __restrict__ isv) {
    size_t R = blockIdx.x;
    float mf = mfin[R];
    float is = isv[R];
    const float* m = mu + R * NCH;
    float* row = align + R * S_;
    __shared__ float fac[NCH];
    if (threadIdx.x < NCH) fac[threadIdx.x] = exp_fast(m[threadIdx.x] - mf) * is;
    __syncthreads();
    for (int i = threadIdx.x * 4; i < S_; i += 256 * 4) {
        float f = fac[i >> 7];
        float4 v = *(float4*)&row[i];
        v.x *= f; v.y *= f; v.z *= f; v.w *= f;
        *(float4*)&row[i] = v;
    }
}

// ---------------------------------------------------------------------------
extern "C" void kernel_launch(void* const* d_in, const int* in_sizes, int n_in,
                              void* d_out, int out_size) {
    const float* q    = (const float*)d_in[0];
    const float* v    = (const float*)d_in[1];
    const float* mask = (const float*)d_in[2];
    const float* wq_w = (const float*)d_in[3];
    const float* wq_b = (const float*)d_in[4];
    const float* wk_w = (const float*)d_in[5];
    const float* wk_b = (const float*)d_in[6];
    const float* wv_w = (const float*)d_in[7];
    const float* wv_b = (const float*)d_in[8];
    const float* wo_w = (const float*)d_in[9];
    const float* wo_b = (const float*)d_in[10];

    float* out = (float*)d_out;
    float* heads = out;
    float* align = out + NTOK;

    float* scratch = nullptr;
    cudaGetSymbolAddress((void**)&scratch, g_scratch);

    __nv_bfloat16* AqH = (__nv_bfloat16*)(scratch + 0 * F_ACT);
    __nv_bfloat16* AqL = (__nv_bfloat16*)(scratch + 1 * F_ACT);
    __nv_bfloat16* AvH = (__nv_bfloat16*)(scratch + 2 * F_ACT);
    __nv_bfloat16* AvL = (__nv_bfloat16*)(scratch + 3 * F_ACT);
    __nv_bfloat16* QsH = (__nv_bfloat16*)(scratch + 4 * F_ACT);
    __nv_bfloat16* QsL = (__nv_bfloat16*)(scratch + 5 * F_ACT);
    __nv_bfloat16* KsH = (__nv_bfloat16*)(scratch + 6 * F_ACT);
    __nv_bfloat16* KsL = (__nv_bfloat16*)(scratch + 7 * F_ACT);
    __nv_bfloat16* VsH = (__nv_bfloat16*)(scratch + 8 * F_ACT);
    __nv_bfloat16* VsL = (__nv_bfloat16*)(scratch + 9 * F_ACT);
    float* wb = scratch + 10 * F_ACT;
    __nv_bfloat16* WqH = (__nv_bfloat16*)(wb + 0 * F_W);
    __nv_bfloat16* WqL = (__nv_bfloat16*)(wb + 1 * F_W);
    __nv_bfloat16* WkH = (__nv_bfloat16*)(wb + 2 * F_W);
    __nv_bfloat16* WkL = (__nv_bfloat16*)(wb + 3 * F_W);
    __nv_bfloat16* WvH = (__nv_bfloat16*)(wb + 4 * F_W);
    __nv_bfloat16* WvL = (__nv_bfloat16*)(wb + 5 * F_W);
    __nv_bfloat16* WoH = (__nv_bfloat16*)(wb + 6 * F_W);
    __nv_bfloat16* WoL = (__nv_bfloat16*)(wb + 7 * F_W);

    // softmax stats scratch (AvH/AvL dead after gemm_split3)
    float* mu_s  = scratch + 2 * F_ACT;
    float* mf_s  = mu_s + (size_t)B_ * H_ * S_ * NCH;
    float* is_s  = mf_s + (size_t)B_ * H_ * S_;

    cudaFuncSetAttribute(gemm_mma, cudaFuncAttributeMaxDynamicSharedMemorySize, GSMEM);
    cudaFuncSetAttribute(gemm_split3, cudaFuncAttributeMaxDynamicSharedMemorySize, GSMEM);
    cudaFuncSetAttribute(flash_attn, cudaFuncAttributeMaxDynamicSharedMemorySize, FL_SMEM);

    int nAct = (int)NTOK;
    int gA = (nAct / 4 + 255) / 256;

    conv_w4<<<dim3(32, 32, 4), dim3(32, 8)>>>(wq_w, wk_w, wv_w, wo_w,
                                              WqH, WqL, WkH, WkL,
                                              WvH, WvL, WoH, WoL);
    conv_act2<<<dim3(gA, 1, 2), 256>>>(q, AqH, AqL, v, AvH, AvL, nAct);

    dim3 gproj3(D_ / 128, (B_ * S_) / 128, 3);
    gemm_split3<<<gproj3, 256, GSMEM>>>(AqH, AqL, AvH, AvL,
                                        WqH, WqL, WkH, WkL, WvH, WvL,
                                        wq_b, wk_b, wv_b,
                                        QsH, QsL, KsH, KsL, VsH, VsL);

    dim3 gfa(S_ / QT, B_ * H_);                   // (16, 32)
    flash_attn<<<gfa, FT, FL_SMEM>>>(QsH, QsL, KsH, KsL, VsH, VsL,
                                     mask, align, mu_s, mf_s, is_s, AqH, AqL);

    fixup<<<B_ * H_ * S_, 256>>>(align, mu_s, mf_s, is_s);

    dim3 gproj(D_ / 128, (B_ * S_) / 128);
    gemm_mma<<<gproj, 256, GSMEM>>>(AqH, AqL, WoH, WoL, wo_b, heads);
}